// round 7
// baseline (speedup 1.0000x reference)
#include <cuda_runtime.h>
#include <cuda_bf16.h>
#include <math.h>
#include <stdint.h>

// ---------------- constants ----------------
#define B_   8
#define C_   768
#define H_   32
#define W_   32
#define T_   1024          // H*W
#define L_   2
#define FF_  3072
#define NPTS 2048          // PH*PW*K
#define TOPK_ 5
#define NCAND 16
#define AROUND_ 5
#define NHEAD_ 8
#define HD_  96

// ---------------- scratch (device globals; allocation-free) ----------------
__device__ float g_pf    [(size_t)B_*NPTS*C_];
__device__ float g_hid   [(size_t)B_*NPTS*C_];   // xT scratch
__device__ float g_coords[(size_t)B_*NPTS*2];
__device__ float g_score [(size_t)B_*NPTS];
__device__ int   g_top16 [B_*NCAND];
__device__ float g_exsc  [B_*NCAND];
__device__ int   g_topidx[B_*TOPK_];
__device__ float g_mem   [(size_t)B_*10*C_];
__device__ float g_tgt   [(size_t)B_*T_*C_];
__device__ float g_tmp   [(size_t)B_*T_*C_];
__device__ float g_qkv   [(size_t)B_*T_*3*C_];
__device__ float g_attn  [(size_t)B_*T_*C_];
__device__ float g_ffh   [(size_t)B_*T_*FF_];
__device__ float g_memkv [(size_t)B_*10*2*C_];
__device__ float g_q     [(size_t)B_*T_*C_];

// ---------------- tf32 mma ----------------
__device__ __forceinline__ void mma8(float* d, const float* a, const float* b){
    asm volatile("mma.sync.aligned.m16n8k8.row.col.f32.tf32.tf32.f32 "
        "{%0,%1,%2,%3},{%4,%5,%6,%7},{%8,%9},{%0,%1,%2,%3};\n"
        : "+f"(d[0]), "+f"(d[1]), "+f"(d[2]), "+f"(d[3])
        : "r"(__float_as_uint(a[0])), "r"(__float_as_uint(a[1])),
          "r"(__float_as_uint(a[2])), "r"(__float_as_uint(a[3])),
          "r"(__float_as_uint(b[0])), "r"(__float_as_uint(b[1])));
}

// ---------------- TF32 MMA GEMM (NN only) ----------------
// SCORE mode: bias+relu, dot with w2[c], row-reduce, atomicAdd into score (no C store).
// Otherwise C = scale*A@B + bias (opt relu). Batched over blockIdx.z.
template<bool RELU, bool SCORE>
__global__ __launch_bounds__(256, 2)
void mma_gemm_kernel(const float* __restrict__ A, const float* __restrict__ B,
                     const float* __restrict__ bias, float* __restrict__ C,
                     const float* __restrict__ w2, float* __restrict__ score,
                     int M, int N, int K, int lda, int ldb, int ldc,
                     long sA1, long sA2, long sB1, long sB2, long sC1, long sC2,
                     float scale)
{
    const int PAD = 136;
    const int SEG = 2 * 16 * PAD;
    __shared__ float smem[2 * SEG];

    int z = blockIdx.z, zb = z >> 3, zh = z & 7;
    A += (size_t)zb * sA1 + (size_t)zh * sA2;
    B += (size_t)zb * sB1 + (size_t)zh * sB2;
    if (!SCORE) C += (size_t)zb * sC1 + (size_t)zh * sC2;

    int tid = threadIdx.x, lane = tid & 31, warp = tid >> 5;
    int gid = lane >> 2, tig = lane & 3;
    int wm = warp >> 2, wn = warp & 3;
    int row0 = blockIdx.y * 128, col0 = blockIdx.x * 128;

    float acc[4][4][4];
    #pragma unroll
    for (int i = 0; i < 4; i++)
        #pragma unroll
        for (int j = 0; j < 4; j++)
            #pragma unroll
            for (int r = 0; r < 4; r++) acc[i][j][r] = 0.f;

    float4 ra[2], rb[2];
    const float4 zero4 = make_float4(0.f,0.f,0.f,0.f);

    auto gload = [&](int k0){
        #pragma unroll
        for (int i = 0; i < 2; i++){
            int idx = tid + 256*i;
            int arow = idx >> 2, ac4 = idx & 3;
            int gr = row0 + arow;
            ra[i] = (gr < M) ? *(const float4*)(A + (size_t)gr*lda + k0 + ac4*4) : zero4;
            int brow = idx >> 5, bc4 = idx & 31;
            int gc = col0 + bc4*4;
            rb[i] = (gc < N) ? *(const float4*)(B + (size_t)(k0 + brow)*ldb + gc) : zero4;
        }
    };

    auto sstore = [&](int buf){
        float* As = smem + buf*SEG;
        float* Bs = As + 16*PAD;
        #pragma unroll
        for (int i = 0; i < 2; i++){
            int idx = tid + 256*i;
            int arow = idx >> 2, ac4 = idx & 3;
            const float* pa = (const float*)&ra[i];
            #pragma unroll
            for (int j = 0; j < 4; j++)
                As[(ac4*4 + j)*PAD + arow] = pa[j];
            int brow = idx >> 5, bc4 = idx & 31;
            *(float4*)&Bs[brow*PAD + bc4*4] = rb[i];
        }
    };

    auto compute = [&](int buf){
        const float* As = smem + buf*SEG;
        const float* Bs = As + 16*PAD;
        #pragma unroll
        for (int kk = 0; kk < 16; kk += 8){
            int k1 = (kk + tig)*PAD, k2 = (kk + tig + 4)*PAD;
            float ah[4][4], bh[4][2];
            #pragma unroll
            for (int ma = 0; ma < 4; ma++){
                int m = wm*64 + ma*16 + gid;
                ah[ma][0] = As[k1 + m];     ah[ma][1] = As[k1 + m + 8];
                ah[ma][2] = As[k2 + m];     ah[ma][3] = As[k2 + m + 8];
            }
            #pragma unroll
            for (int na = 0; na < 4; na++){
                int n = wn*32 + na*8 + gid;
                bh[na][0] = Bs[k1 + n]; bh[na][1] = Bs[k2 + n];
            }
            #pragma unroll
            for (int ma = 0; ma < 4; ma++)
                #pragma unroll
                for (int na = 0; na < 4; na++)
                    mma8(acc[ma][na], ah[ma], bh[na]);
        }
    };

    int nk = K / 16;
    gload(0); sstore(0); __syncthreads();
    for (int it = 0; it < nk; it++){
        if (it + 1 < nk) gload((it + 1)*16);
        compute(it & 1);
        if (it + 1 < nk){ __syncthreads(); sstore((it + 1)&1); __syncthreads(); }
    }

    #pragma unroll
    for (int ma = 0; ma < 4; ma++){
        int r0 = row0 + wm*64 + ma*16 + gid;
        float s0 = 0.f, s1 = 0.f;
        #pragma unroll
        for (int na = 0; na < 4; na++){
            int c = col0 + wn*32 + na*8 + 2*tig;
            if (c >= N) continue;
            float b0 = bias ? bias[c] : 0.f;
            float b1 = bias ? bias[c+1] : 0.f;
            float x0 = acc[ma][na][0]*scale + b0;
            float x1 = acc[ma][na][1]*scale + b1;
            float x2 = acc[ma][na][2]*scale + b0;
            float x3 = acc[ma][na][3]*scale + b1;
            if (RELU || SCORE){
                x0 = fmaxf(x0, 0.f); x1 = fmaxf(x1, 0.f);
                x2 = fmaxf(x2, 0.f); x3 = fmaxf(x3, 0.f);
            }
            if (SCORE){
                float w0 = w2[c], w1 = w2[c+1];
                s0 += x0*w0 + x1*w1;
                s1 += x2*w0 + x3*w1;
            } else {
                if (r0 < M){ float2 o = make_float2(x0, x1); *(float2*)&C[(size_t)r0*ldc + c] = o; }
                if (r0 + 8 < M){ float2 o = make_float2(x2, x3); *(float2*)&C[(size_t)(r0+8)*ldc + c] = o; }
            }
        }
        if (SCORE){
            s0 += __shfl_xor_sync(0xffffffffu, s0, 1);
            s0 += __shfl_xor_sync(0xffffffffu, s0, 2);
            s1 += __shfl_xor_sync(0xffffffffu, s1, 1);
            s1 += __shfl_xor_sync(0xffffffffu, s1, 2);
            if (tig == 0){
                if (r0 < M)     atomicAdd(&score[r0], s0);
                if (r0 + 8 < M) atomicAdd(&score[r0 + 8], s1);
            }
        }
    }
}

static void mma_gemm(const float* A, const float* B, const float* bias, float* C,
                     int M, int N, int K, int lda, int ldb, int ldc, int gz,
                     long sA1, long sA2, long sB1, long sB2, long sC1, long sC2,
                     float scale, bool relu){
    dim3 grid((N + 127)/128, (M + 127)/128, gz);
    if (relu)
        mma_gemm_kernel<true,false><<<grid,256>>>(A,B,bias,C,nullptr,nullptr,M,N,K,lda,ldb,ldc,sA1,sA2,sB1,sB2,sC1,sC2,scale);
    else
        mma_gemm_kernel<false,false><<<grid,256>>>(A,B,bias,C,nullptr,nullptr,M,N,K,lda,ldb,ldc,sA1,sA2,sB1,sB2,sC1,sC2,scale);
}

static void mma_gemm_score(const float* A, const float* B, const float* bias,
                           const float* w2, float* score, int M, int N, int K,
                           int lda, int ldb){
    dim3 grid((N + 127)/128, (M + 127)/128, 1);
    mma_gemm_kernel<true,true><<<grid,256>>>(A,B,bias,nullptr,w2,score,M,N,K,lda,ldb,0,0,0,0,0,0,0,1.f);
}

// ---------------- flash attention (tf32 MMA, online softmax) ----------------
#define FA_PADK 136
#define FA_PADV 104
#define FA_LOG2E 1.4426950408889634f

__global__ __launch_bounds__(256, 1)
void flash_attn_kernel(const float* __restrict__ qkv, float* __restrict__ out){
    extern __shared__ float sm[];
    float* Ks = sm;
    float* Vs = Ks + 96*FA_PADK;
    float* Ps = Vs + 128*FA_PADV;

    int qt = blockIdx.x, bh = blockIdx.y, b = bh >> 3, h = bh & 7;
    int tid = threadIdx.x, lane = tid & 31, warp = tid >> 5;
    int gid = lane >> 2, tig = lane & 3;
    int m0 = warp * 16;
    int q0 = qt * 128;
    const float iscale = 0.10206207261596577f;

    float qf[12][4];
    {
        const float* Qa = qkv + (size_t)(b*T_ + q0 + m0 + gid)*(3*C_) + h*HD_;
        const float* Qb = Qa + 8*(3*C_);
        #pragma unroll
        for (int kk = 0; kk < 12; kk++){
            qf[kk][0] = Qa[kk*8 + tig]     * iscale;
            qf[kk][1] = Qb[kk*8 + tig]     * iscale;
            qf[kk][2] = Qa[kk*8 + tig + 4] * iscale;
            qf[kk][3] = Qb[kk*8 + tig + 4] * iscale;
        }
    }

    float oacc[12][4];
    #pragma unroll
    for (int i = 0; i < 12; i++)
        #pragma unroll
        for (int j = 0; j < 4; j++) oacc[i][j] = 0.f;
    float mrow0 = -1e30f, mrow1 = -1e30f, lrow0 = 0.f, lrow1 = 0.f;

    for (int kt = 0; kt < 8; kt++){
        __syncthreads();
        {
            const float* Kb = qkv + (size_t)(b*T_ + kt*128)*(3*C_) + C_ + h*HD_;
            const float* Vb = Kb + C_;
            for (int idx = tid; idx < 128*24; idx += 256){
                int r = idx / 24, c4 = idx % 24;
                float4 kv4 = *(const float4*)(Kb + (size_t)r*(3*C_) + c4*4);
                Ks[(c4*4+0)*FA_PADK + r] = kv4.x;
                Ks[(c4*4+1)*FA_PADK + r] = kv4.y;
                Ks[(c4*4+2)*FA_PADK + r] = kv4.z;
                Ks[(c4*4+3)*FA_PADK + r] = kv4.w;
                float4 vv4 = *(const float4*)(Vb + (size_t)r*(3*C_) + c4*4);
                *(float4*)&Vs[r*FA_PADV + c4*4] = vv4;
            }
        }
        __syncthreads();

        float sacc[16][4];
        #pragma unroll
        for (int nf = 0; nf < 16; nf++)
            #pragma unroll
            for (int j = 0; j < 4; j++) sacc[nf][j] = 0.f;
        #pragma unroll
        for (int kk = 0; kk < 12; kk++){
            int k1 = (kk*8 + tig)*FA_PADK, k2 = (kk*8 + tig + 4)*FA_PADK;
            #pragma unroll
            for (int nf = 0; nf < 16; nf++){
                float bfr[2] = { Ks[k1 + nf*8 + gid], Ks[k2 + nf*8 + gid] };
                mma8(sacc[nf], qf[kk], bfr);
            }
        }

        float rm0 = -1e30f, rm1 = -1e30f;
        #pragma unroll
        for (int nf = 0; nf < 16; nf++){
            rm0 = fmaxf(rm0, fmaxf(sacc[nf][0], sacc[nf][1]));
            rm1 = fmaxf(rm1, fmaxf(sacc[nf][2], sacc[nf][3]));
        }
        rm0 = fmaxf(rm0, __shfl_xor_sync(0xffffffffu, rm0, 1));
        rm0 = fmaxf(rm0, __shfl_xor_sync(0xffffffffu, rm0, 2));
        rm1 = fmaxf(rm1, __shfl_xor_sync(0xffffffffu, rm1, 1));
        rm1 = fmaxf(rm1, __shfl_xor_sync(0xffffffffu, rm1, 2));
        float mn0 = fmaxf(mrow0, rm0), mn1 = fmaxf(mrow1, rm1);
        float al0 = exp2f((mrow0 - mn0)*FA_LOG2E);
        float al1 = exp2f((mrow1 - mn1)*FA_LOG2E);
        mrow0 = mn0; mrow1 = mn1;
        float rs0 = 0.f, rs1 = 0.f;
        #pragma unroll
        for (int nf = 0; nf < 16; nf++){
            float p0 = exp2f((sacc[nf][0] - mn0)*FA_LOG2E);
            float p1 = exp2f((sacc[nf][1] - mn0)*FA_LOG2E);
            float p2 = exp2f((sacc[nf][2] - mn1)*FA_LOG2E);
            float p3 = exp2f((sacc[nf][3] - mn1)*FA_LOG2E);
            sacc[nf][0] = p0; sacc[nf][1] = p1; sacc[nf][2] = p2; sacc[nf][3] = p3;
            rs0 += p0 + p1; rs1 += p2 + p3;
        }
        rs0 += __shfl_xor_sync(0xffffffffu, rs0, 1);
        rs0 += __shfl_xor_sync(0xffffffffu, rs0, 2);
        rs1 += __shfl_xor_sync(0xffffffffu, rs1, 1);
        rs1 += __shfl_xor_sync(0xffffffffu, rs1, 2);
        lrow0 = lrow0*al0 + rs0;
        lrow1 = lrow1*al1 + rs1;
        #pragma unroll
        for (int nf = 0; nf < 12; nf++){
            oacc[nf][0] *= al0; oacc[nf][1] *= al0;
            oacc[nf][2] *= al1; oacc[nf][3] *= al1;
        }

        #pragma unroll
        for (int nf = 0; nf < 16; nf++){
            int c = nf*8 + 2*tig;
            Ps[(size_t)c*FA_PADK     + m0 + gid]     = sacc[nf][0];
            Ps[(size_t)(c+1)*FA_PADK + m0 + gid]     = sacc[nf][1];
            Ps[(size_t)c*FA_PADK     + m0 + gid + 8] = sacc[nf][2];
            Ps[(size_t)(c+1)*FA_PADK + m0 + gid + 8] = sacc[nf][3];
        }
        __syncwarp();

        #pragma unroll
        for (int kk = 0; kk < 16; kk++){
            int k1 = (kk*8 + tig)*FA_PADK, k2 = (kk*8 + tig + 4)*FA_PADK;
            float pa[4] = { Ps[k1 + m0 + gid], Ps[k1 + m0 + gid + 8],
                            Ps[k2 + m0 + gid], Ps[k2 + m0 + gid + 8] };
            int v1 = (kk*8 + tig)*FA_PADV, v2 = (kk*8 + tig + 4)*FA_PADV;
            #pragma unroll
            for (int nf = 0; nf < 12; nf++){
                float vb2[2] = { Vs[v1 + nf*8 + gid], Vs[v2 + nf*8 + gid] };
                mma8(oacc[nf], pa, vb2);
            }
        }
    }

    float inv0 = 1.f / lrow0, inv1 = 1.f / lrow1;
    size_t r0 = (size_t)(b*T_ + q0 + m0 + gid);
    #pragma unroll
    for (int nf = 0; nf < 12; nf++){
        int col = h*HD_ + nf*8 + 2*tig;
        float2 o0 = make_float2(oacc[nf][0]*inv0, oacc[nf][1]*inv0);
        float2 o1 = make_float2(oacc[nf][2]*inv1, oacc[nf][3]*inv1);
        *(float2*)&out[r0*C_ + col]       = o0;
        *(float2*)&out[(r0 + 8)*C_ + col] = o1;
    }
}

// ---------------- bilinear helpers ----------------
__device__ __forceinline__ float bilin_img(const float* __restrict__ img, float ix, float iy){
    float x0f = floorf(ix), y0f = floorf(iy);
    int x0 = (int)x0f, y0 = (int)y0f;
    float wx1 = ix - x0f, wy1 = iy - y0f;
    float wx0 = 1.f - wx1, wy0 = 1.f - wy1;
    float v = 0.f;
    bool vx0 = (x0 >= 0) & (x0 < 32);
    bool vx1 = (x0 + 1 >= 0) & (x0 + 1 < 32);
    bool vy0 = (y0 >= 0) & (y0 < 32);
    bool vy1 = (y0 + 1 >= 0) & (y0 + 1 < 32);
    if (vx0 & vy0) v += img[y0*32 + x0]         * wx0 * wy0;
    if (vx1 & vy0) v += img[y0*32 + x0 + 1]     * wx1 * wy0;
    if (vx0 & vy1) v += img[(y0+1)*32 + x0]     * wx0 * wy1;
    if (vx1 & vy1) v += img[(y0+1)*32 + x0 + 1] * wx1 * wy1;
    return v;
}
__device__ __forceinline__ float bilin_pe(const float* __restrict__ pe, float ix, float iy, int c){
    float x0f = floorf(ix), y0f = floorf(iy);
    int x0 = (int)x0f, y0 = (int)y0f;
    float wx1 = ix - x0f, wy1 = iy - y0f;
    float wx0 = 1.f - wx1, wy0 = 1.f - wy1;
    float v = 0.f;
    bool vx0 = (x0 >= 0) & (x0 < 32);
    bool vx1 = (x0 + 1 >= 0) & (x0 + 1 < 32);
    bool vy0 = (y0 >= 0) & (y0 < 32);
    bool vy1 = (y0 + 1 >= 0) & (y0 + 1 < 32);
    if (vx0 & vy0) v += pe[((size_t)(y0*32 + x0))*C_ + c]         * wx0 * wy0;
    if (vx1 & vy0) v += pe[((size_t)(y0*32 + x0 + 1))*C_ + c]     * wx1 * wy0;
    if (vx0 & vy1) v += pe[((size_t)((y0+1)*32 + x0))*C_ + c]     * wx0 * wy1;
    if (vx1 & vy1) v += pe[((size_t)((y0+1)*32 + x0 + 1))*C_ + c] * wx1 * wy1;
    return v;
}

// ---------------- transpose x [B,C,T] -> xT [B,T,C] ----------------
__global__ void transpose_in_kernel(const float* __restrict__ x, float* __restrict__ xT){
    __shared__ float tile[32][33];
    int c0 = blockIdx.x*32, t0 = blockIdx.y*32, b = blockIdx.z;
    for (int i = threadIdx.y; i < 32; i += 8)
        tile[i][threadIdx.x] = x[((size_t)b*C_ + c0 + i)*T_ + t0 + threadIdx.x];
    __syncthreads();
    for (int i = threadIdx.y; i < 32; i += 8)
        xT[((size_t)b*T_ + t0 + i)*C_ + c0 + threadIdx.x] = tile[threadIdx.x][i];
}

// ---------------- blockwise sampling from xT ----------------
__global__ void sample_kernel(const float* __restrict__ xT, const float* __restrict__ brand,
                              float* __restrict__ pf, float* __restrict__ coords){
    int p0 = blockIdx.x * 16;
    __shared__ int   sidx[16][4];
    __shared__ float swt [16][4];
    int tid = threadIdx.x;
    if (tid < 16){
        int bn = p0 + tid;
        int b  = bn >> 11;
        int n  = bn & 2047;
        int k  = n & 1;
        int pw = (n >> 1) & 31;
        int ph = n >> 6;
        const float bs = 0.0625f;
        const float* br = brand + ((((size_t)b*32 + ph)*32 + pw)*2 + k)*2;
        float gx = br[0]*bs + (-1.0f + ph*bs);
        float gy = br[1]*bs + (-1.0f + pw*bs);
        coords[(size_t)bn*2]     = gx;
        coords[(size_t)bn*2 + 1] = gy;
        float ix = ((gx + 1.0f)*32.0f - 1.0f)*0.5f;
        float iy = ((gy + 1.0f)*32.0f - 1.0f)*0.5f;
        float x0f = floorf(ix), y0f = floorf(iy);
        int x0 = (int)x0f, y0 = (int)y0f;
        float wx1 = ix - x0f, wy1 = iy - y0f;
        float wxs[2] = {1.f - wx1, wx1};
        float wys[2] = {1.f - wy1, wy1};
        #pragma unroll
        for (int j = 0; j < 4; j++){
            int xi = x0 + (j & 1), yi = y0 + (j >> 1);
            bool v = (xi >= 0) & (xi < 32) & (yi >= 0) & (yi < 32);
            sidx[tid][j] = v ? (yi*32 + xi) : 0;
            swt [tid][j] = v ? (wxs[j & 1]*wys[j >> 1]) : 0.f;
        }
    }
    __syncthreads();
    int b = (p0 >> 11);
    const float* base = xT + (size_t)b*T_*C_;
    for (int pt = 0; pt < 16; pt++){
        const float* r0 = base + (size_t)sidx[pt][0]*C_;
        const float* r1 = base + (size_t)sidx[pt][1]*C_;
        const float* r2 = base + (size_t)sidx[pt][2]*C_;
        const float* r3 = base + (size_t)sidx[pt][3]*C_;
        float w0 = swt[pt][0], w1 = swt[pt][1], w2 = swt[pt][2], w3 = swt[pt][3];
        float* dst = pf + (size_t)(p0 + pt)*C_;
        for (int c = tid; c < C_; c += 256)
            dst[c] = r0[c]*w0 + r1[c]*w1 + r2[c]*w2 + r3[c]*w3;
    }
}

// ---------------- zero score ----------------
__global__ void zero_score_kernel(float* __restrict__ score){
    int i = blockIdx.x*256 + threadIdx.x;
    if (i < B_*NPTS) score[i] = 0.f;
}

// ---------------- top-K (approx candidates) ----------------
__global__ void topk_kernel(const float* __restrict__ score, int* __restrict__ topidx, int K){
    int b = blockIdx.x;
    __shared__ float sv[2048];
    __shared__ float rv[256];
    __shared__ int   ri[256];
    for (int j = threadIdx.x; j < 2048; j += 256) sv[j] = score[(size_t)b*2048 + j];
    __syncthreads();
    for (int t = 0; t < K; t++){
        float bv = -1e30f; int bi = 0x7fffffff;
        for (int j = threadIdx.x; j < 2048; j += 256){
            float v = sv[j];
            if (v > bv){ bv = v; bi = j; }
        }
        rv[threadIdx.x] = bv; ri[threadIdx.x] = bi;
        __syncthreads();
        for (int s = 128; s; s >>= 1){
            if (threadIdx.x < s){
                float v2 = rv[threadIdx.x + s]; int i2 = ri[threadIdx.x + s];
                if (v2 > rv[threadIdx.x] || (v2 == rv[threadIdx.x] && i2 < ri[threadIdx.x])){
                    rv[threadIdx.x] = v2; ri[threadIdx.x] = i2;
                }
            }
            __syncthreads();
        }
        if (threadIdx.x == 0){
            topidx[b*K + t] = ri[0];
            sv[ri[0]] = -1e30f;
        }
        __syncthreads();
    }
}

// ---------------- exact fp32 rescore of candidates ----------------
__global__ __launch_bounds__(256)
void rescore_kernel(const float* __restrict__ pf, const float* __restrict__ W1,
                    const float* __restrict__ b1, const float* __restrict__ w2,
                    const int* __restrict__ cand, float* __restrict__ exsc){
    int b = blockIdx.x >> 4, c = blockIdx.x & 15;
    int idx = cand[b*NCAND + c];
    __shared__ float spf[C_];
    int tid = threadIdx.x;
    for (int i = tid; i < C_; i += 256) spf[i] = pf[((size_t)b*NPTS + idx)*C_ + i];
    __syncthreads();
    float a0 = b1[tid], a1 = b1[tid+256], a2 = b1[tid+512];
    for (int k = 0; k < C_; k++){
        float v = spf[k];
        const float* w = W1 + (size_t)k*C_;
        a0 += v * w[tid];
        a1 += v * w[tid+256];
        a2 += v * w[tid+512];
    }
    float p = fmaxf(a0,0.f)*w2[tid] + fmaxf(a1,0.f)*w2[tid+256] + fmaxf(a2,0.f)*w2[tid+512];
    #pragma unroll
    for (int o = 16; o; o >>= 1) p += __shfl_down_sync(0xffffffffu, p, o);
    __shared__ float red[8];
    if ((tid & 31) == 0) red[tid >> 5] = p;
    __syncthreads();
    if (tid == 0){
        float s = 0.f;
        #pragma unroll
        for (int i = 0; i < 8; i++) s += red[i];
        exsc[b*NCAND + c] = s;
    }
}

// ---------------- final exact top-5 over candidates ----------------
__global__ void final_top5_kernel(const float* __restrict__ exsc, const int* __restrict__ cand,
                                  int* __restrict__ topidx){
    int b = blockIdx.x;
    if (threadIdx.x == 0){
        float s[NCAND]; int id[NCAND];
        for (int i = 0; i < NCAND; i++){ s[i] = exsc[b*NCAND + i]; id[i] = cand[b*NCAND + i]; }
        for (int t = 0; t < TOPK_; t++){
            int bi = 0;
            float bv = -1e30f; int bid = 0x7fffffff;
            for (int i = 0; i < NCAND; i++){
                if (s[i] > bv || (s[i] == bv && id[i] < bid)){ bv = s[i]; bid = id[i]; bi = i; }
            }
            topidx[b*TOPK_ + t] = id[bi];
            s[bi] = -1e30f;
        }
    }
}

// ---------------- soft_align ----------------
__global__ void soft_align_kernel(const float* __restrict__ mainx, const float* __restrict__ pe,
                                  const float* __restrict__ arand, const float* __restrict__ mqrow,
                                  const float* __restrict__ pf, const float* __restrict__ coords,
                                  const int* __restrict__ topidx, float* __restrict__ memo, int rowBase){
    int b  = blockIdx.x / TOPK_;
    int nk = blockIdx.x % TOPK_;
    int idx = topidx[b*TOPK_ + nk];
    float px = coords[((size_t)b*NPTS + idx)*2 + 0];
    float py = coords[((size_t)b*NPTS + idx)*2 + 1];
    __shared__ float semb[AROUND_*C_];
    __shared__ float red[256];
    __shared__ float res[11];
    __shared__ float sw[AROUND_];
    float ixs[AROUND_], iys[AROUND_];
    #pragma unroll
    for (int a = 0; a < AROUND_; a++){
        const float* ar = arand + (((size_t)b*AROUND_ + a)*TOPK_ + nk)*2;
        float g0 = px + (ar[0]*2.f - 0.5f)*0.2f;
        float g1 = py + (ar[1]*2.f - 0.5f)*0.2f;
        g0 = fminf(fmaxf(g0, -1.f), 1.f);
        g1 = fminf(fmaxf(g1, -1.f), 1.f);
        ixs[a] = ((g0 + 1.f)*32.f - 1.f)*0.5f;
        iys[a] = ((g1 + 1.f)*32.f - 1.f)*0.5f;
    }
    const float* pfrow = pf + ((size_t)b*NPTS + idx)*C_;
    float rep2 = 0.f, num[AROUND_], af2[AROUND_];
    #pragma unroll
    for (int a = 0; a < AROUND_; a++){ num[a] = 0.f; af2[a] = 0.f; }
    for (int c = threadIdx.x; c < C_; c += 256){
        float r = pfrow[c];
        rep2 += r*r;
        const float* img = mainx + ((size_t)b*C_ + c)*T_;
        #pragma unroll
        for (int a = 0; a < AROUND_; a++){
            float af = bilin_img(img, ixs[a], iys[a]);
            num[a] += r*af;
            af2[a] += af*af;
            semb[a*C_ + c] = bilin_pe(pe, ixs[a], iys[a], c);
        }
    }
    float vals[11];
    vals[0] = rep2;
    #pragma unroll
    for (int a = 0; a < AROUND_; a++){ vals[1+a] = num[a]; vals[6+a] = af2[a]; }
    for (int v = 0; v < 11; v++){
        red[threadIdx.x] = vals[v];
        __syncthreads();
        for (int s = 128; s; s >>= 1){
            if (threadIdx.x < s) red[threadIdx.x] += red[threadIdx.x + s];
            __syncthreads();
        }
        if (threadIdx.x == 0) res[v] = red[0];
        __syncthreads();
    }
    if (threadIdx.x == 0){
        float rn = fmaxf(sqrtf(res[0]), 1e-8f);
        float s[AROUND_]; float mx = -1e30f;
        for (int a = 0; a < AROUND_; a++){
            s[a] = res[1+a] / (rn * fmaxf(sqrtf(res[6+a]), 1e-8f));
            mx = fmaxf(mx, s[a]);
        }
        float ss = 0.f;
        for (int a = 0; a < AROUND_; a++){ s[a] = expf(s[a] - mx); ss += s[a]; }
        for (int a = 0; a < AROUND_; a++) sw[a] = s[a] / ss;
    }
    __syncthreads();
    float w0 = sw[0], w1 = sw[1], w2 = sw[2], w3 = sw[3], w4 = sw[4];
    for (int c = threadIdx.x; c < C_; c += 256){
        float o = pfrow[c] + mqrow[c];
        o += semb[0*C_ + c]*w0 + semb[1*C_ + c]*w1 + semb[2*C_ + c]*w2
           + semb[3*C_ + c]*w3 + semb[4*C_ + c]*w4;
        memo[((size_t)b*10 + rowBase + nk)*C_ + c] = o;
    }
}

// ---------------- tgt init ----------------
__global__ void tgt_init_kernel(const float* __restrict__ mainx, const float* __restrict__ mq,
                                const float* __restrict__ pe, float* __restrict__ tgt){
    __shared__ float tile[32][33];
    int c0 = blockIdx.x*32, t0 = blockIdx.y*32, b = blockIdx.z;
    for (int i = threadIdx.y; i < 32; i += 8)
        tile[i][threadIdx.x] = mainx[((size_t)b*C_ + c0 + i)*T_ + t0 + threadIdx.x];
    __syncthreads();
    for (int i = threadIdx.y; i < 32; i += 8){
        int t = t0 + i, c = c0 + threadIdx.x;
        tgt[((size_t)b*T_ + t)*C_ + c] = tile[threadIdx.x][i] + mq[c] + pe[(size_t)t*C_ + c];
    }
}

// ---------------- cross-attention (10 keys) ----------------
__global__ void ca_attn_kernel(const float* __restrict__ q, const float* __restrict__ kv,
                               float* __restrict__ out){
    int bh = blockIdx.y, b = bh >> 3, h = bh & 7;
    int i = blockIdx.x*256 + threadIdx.x;
    __shared__ float Ks[10][96];
    __shared__ float Vsm[10][96];
    for (int idx = threadIdx.x; idx < 960; idx += 256){
        int j = idx / 96, d = idx % 96;
        Ks[j][d]  = kv[((size_t)b*10 + j)*(2*C_) + h*HD_ + d];
        Vsm[j][d] = kv[((size_t)b*10 + j)*(2*C_) + C_ + h*HD_ + d];
    }
    __syncthreads();
    const float* qr = q + ((size_t)b*T_ + i)*C_ + h*HD_;
    float s[10];
    #pragma unroll
    for (int j = 0; j < 10; j++) s[j] = 0.f;
    for (int d = 0; d < HD_; d++){
        float qd = qr[d];
        #pragma unroll
        for (int j = 0; j < 10; j++) s[j] += qd * Ks[j][d];
    }
    const float scale = 0.10206207261596577f;
    float mx = -1e30f;
    #pragma unroll
    for (int j = 0; j < 10; j++){ s[j] *= scale; mx = fmaxf(mx, s[j]); }
    float sum = 0.f;
    #pragma unroll
    for (int j = 0; j < 10; j++){ s[j] = expf(s[j] - mx); sum += s[j]; }
    float inv = 1.f / sum;
    #pragma unroll
    for (int j = 0; j < 10; j++) s[j] *= inv;
    float* orow = out + ((size_t)b*T_ + i)*C_ + h*HD_;
    for (int d = 0; d < HD_; d++){
        float o = 0.f;
        #pragma unroll
        for (int j = 0; j < 10; j++) o += s[j] * Vsm[j][d];
        orow[d] = o;
    }
}

// ---------------- residual add + layernorm ----------------
__global__ void add_ln_kernel(float* __restrict__ tgt, const float* __restrict__ resid,
                              const float* __restrict__ w, const float* __restrict__ bb){
    int row = blockIdx.x, t = threadIdx.x;
    float* p = tgt + (size_t)row*C_;
    const float* r = resid + (size_t)row*C_;
    float v[3];
    float sum = 0.f;
    #pragma unroll
    for (int i = 0; i < 3; i++){ v[i] = p[t + i*256] + r[t + i*256]; sum += v[i]; }
    __shared__ float red[256];
    red[t] = sum; __syncthreads();
    for (int s = 128; s; s >>= 1){ if (t < s) red[t] += red[t + s]; __syncthreads(); }
    float m = red[0] * (1.f/768.f);
    __syncthreads();
    float s2 = 0.f;
    #pragma unroll
    for (int i = 0; i < 3; i++){ float d = v[i] - m; s2 += d*d; }
    red[t] = s2; __syncthreads();
    for (int s = 128; s; s >>= 1){ if (t < s) red[t] += red[t + s]; __syncthreads(); }
    float var = red[0] * (1.f/768.f);
    float rstd = rsqrtf(var + 1e-5f);
    #pragma unroll
    for (int i = 0; i < 3; i++){
        int c = t + i*256;
        p[c] = (v[i] - m)*rstd*w[c] + bb[c];
    }
}

// ---------------- final transpose ----------------
__global__ void transpose_out_kernel(const float* __restrict__ tgt, float* __restrict__ out){
    __shared__ float tile[32][33];
    int c0 = blockIdx.x*32, t0 = blockIdx.y*32, b = blockIdx.z;
    for (int i = threadIdx.y; i < 32; i += 8)
        tile[i][threadIdx.x] = tgt[((size_t)b*T_ + t0 + i)*C_ + c0 + threadIdx.x];
    __syncthreads();
    for (int i = threadIdx.y; i < 32; i += 8)
        out[((size_t)b*C_ + c0 + i)*T_ + t0 + threadIdx.x] = tile[threadIdx.x][i];
}

// ---------------- launch ----------------
extern "C" void kernel_launch(void* const* d_in, const int* in_sizes, int n_in,
                              void* d_out, int out_size){
    const float* mainx      = (const float*)d_in[0];
    const float* others[2]  = {(const float*)d_in[1], (const float*)d_in[2]};
    const float* pe         = (const float*)d_in[3];
    const float* mq         = (const float*)d_in[4];
    const float* s_w1       = (const float*)d_in[5];
    const float* s_b1       = (const float*)d_in[6];
    const float* s_w2       = (const float*)d_in[7];
    const float* s_b2       = (const float*)d_in[8];
    const float* sa_in_w    = (const float*)d_in[9];
    const float* sa_in_b    = (const float*)d_in[10];
    const float* sa_out_w   = (const float*)d_in[11];
    const float* sa_out_b   = (const float*)d_in[12];
    const float* ca_in_w    = (const float*)d_in[13];
    const float* ca_in_b    = (const float*)d_in[14];
    const float* ca_out_w   = (const float*)d_in[15];
    const float* ca_out_b   = (const float*)d_in[16];
    const float* ff1_w      = (const float*)d_in[17];
    const float* ff1_b      = (const float*)d_in[18];
    const float* ff2_w      = (const float*)d_in[19];
    const float* ff2_b      = (const float*)d_in[20];
    const float* ln_w       = (const float*)d_in[21];
    const float* ln_b       = (const float*)d_in[22];
    const float* block_rand = (const float*)d_in[23];
    const float* around_rand= (const float*)d_in[24];
    float* out = (float*)d_out;

    float *pf, *hid, *coords, *score, *memb, *tgt, *tmp, *qkv, *attn, *ffh, *memkv, *qb, *exsc;
    int *topidx, *top16;
    cudaGetSymbolAddress((void**)&pf,     g_pf);
    cudaGetSymbolAddress((void**)&hid,    g_hid);
    cudaGetSymbolAddress((void**)&coords, g_coords);
    cudaGetSymbolAddress((void**)&score,  g_score);
    cudaGetSymbolAddress((void**)&top16,  g_top16);
    cudaGetSymbolAddress((void**)&exsc,   g_exsc);
    cudaGetSymbolAddress((void**)&topidx, g_topidx);
    cudaGetSymbolAddress((void**)&memb,   g_mem);
    cudaGetSymbolAddress((void**)&tgt,    g_tgt);
    cudaGetSymbolAddress((void**)&tmp,    g_tmp);
    cudaGetSymbolAddress((void**)&qkv,    g_qkv);
    cudaGetSymbolAddress((void**)&attn,   g_attn);
    cudaGetSymbolAddress((void**)&ffh,    g_ffh);
    cudaGetSymbolAddress((void**)&memkv,  g_memkv);
    cudaGetSymbolAddress((void**)&qb,     g_q);

    const int FA_SMEM = (96*FA_PADK + 128*FA_PADV + 128*FA_PADK) * 4;
    cudaFuncSetAttribute(flash_attn_kernel, cudaFuncAttributeMaxDynamicSharedMemorySize, FA_SMEM);

    // ---- phase A: modalities ----
    for (int i = 0; i < 2; i++){
        {
            dim3 g(C_/32, T_/32, B_); dim3 bl(32, 8);
            transpose_in_kernel<<<g, bl>>>(others[i], hid);
        }
        sample_kernel<<<B_*NPTS/16, 256>>>(hid, block_rand + (size_t)i*B_*32*32*2*2, pf, coords);
        zero_score_kernel<<<(B_*NPTS + 255)/256, 256>>>(score);
        mma_gemm_score(pf, s_w1, s_b1, s_w2, score, B_*NPTS, C_, C_, C_, C_);
        topk_kernel<<<B_, 256>>>(score, top16, NCAND);
        rescore_kernel<<<B_*NCAND, 256>>>(pf, s_w1, s_b1, s_w2, top16, exsc);
        final_top5_kernel<<<B_, 32>>>(exsc, top16, topidx);
        soft_align_kernel<<<B_*TOPK_, 256>>>(mainx, pe,
                                             around_rand + (size_t)i*B_*AROUND_*TOPK_*2,
                                             mq + (size_t)(i+1)*C_,
                                             pf, coords, topidx, memb, i*TOPK_);
    }

    // ---- tgt init ----
    {
        dim3 g(C_/32, T_/32, B_); dim3 bl(32, 8);
        tgt_init_kernel<<<g, bl>>>(mainx, mq, pe, tgt);
    }

    // ---- decoder layers ----
    for (int l = 0; l < L_; l++){
        mma_gemm(tgt, sa_in_w + (size_t)l*C_*3*C_, sa_in_b + (size_t)l*3*C_, qkv,
                 B_*T_, 3*C_, C_, C_, 3*C_, 3*C_, 1, 0,0,0,0,0,0, 1.f, false);
        {
            dim3 g(T_/128, B_*NHEAD_);
            flash_attn_kernel<<<g, 256, FA_SMEM>>>(qkv, attn);
        }
        mma_gemm(attn, sa_out_w + (size_t)l*C_*C_, sa_out_b + (size_t)l*C_, tmp,
                 B_*T_, C_, C_, C_, C_, C_, 1, 0,0,0,0,0,0, 1.f, false);
        add_ln_kernel<<<B_*T_, 256>>>(tgt, tmp, ln_w + (size_t)(l*3+0)*C_, ln_b + (size_t)(l*3+0)*C_);

        mma_gemm(tgt, ca_in_w + (size_t)l*C_*3*C_, ca_in_b + (size_t)l*3*C_, qb,
                 B_*T_, C_, C_, C_, 3*C_, C_, 1, 0,0,0,0,0,0, 1.f, false);
        mma_gemm(memb, ca_in_w + (size_t)l*C_*3*C_ + C_, ca_in_b + (size_t)l*3*C_ + C_, memkv,
                 B_*10, 2*C_, C_, C_, 3*C_, 2*C_, 1, 0,0,0,0,0,0, 1.f, false);
        { dim3 g(T_/256, B_*NHEAD_); ca_attn_kernel<<<g, 256>>>(qb, memkv, attn); }
        mma_gemm(attn, ca_out_w + (size_t)l*C_*C_, ca_out_b + (size_t)l*C_, tmp,
                 B_*T_, C_, C_, C_, C_, C_, 1, 0,0,0,0,0,0, 1.f, false);
        add_ln_kernel<<<B_*T_, 256>>>(tgt, tmp, ln_w + (size_t)(l*3+1)*C_, ln_b + (size_t)(l*3+1)*C_);

        mma_gemm(tgt, ff1_w + (size_t)l*C_*FF_, ff1_b + (size_t)l*FF_, ffh,
                 B_*T_, FF_, C_, C_, FF_, FF_, 1, 0,0,0,0,0,0, 1.f, true);
        mma_gemm(ffh, ff2_w + (size_t)l*FF_*C_, ff2_b + (size_t)l*C_, tmp,
                 B_*T_, C_, FF_, FF_, C_, C_, 1, 0,0,0,0,0,0, 1.f, false);
        add_ln_kernel<<<B_*T_, 256>>>(tgt, tmp, ln_w + (size_t)(l*3+2)*C_, ln_b + (size_t)(l*3+2)*C_);
    }

    // ---- output transpose ----
    {
        dim3 g(C_/32, T_/32, B_); dim3 bl(32, 8);
        transpose_out_kernel<<<g, bl>>>(tgt, out);
    }
}

// round 8
// speedup vs baseline: 1.2929x; 1.2929x over previous
#include <cuda_runtime.h>
#include <cuda_bf16.h>
#include <math.h>
#include <stdint.h>

// ---------------- constants ----------------
#define B_   8
#define C_   768
#define H_   32
#define W_   32
#define T_   1024          // H*W
#define L_   2
#define FF_  3072
#define NPTS 2048          // PH*PW*K
#define TOPK_ 5
#define NCAND 16
#define AROUND_ 5
#define NHEAD_ 8
#define HD_  96

// ---------------- scratch (device globals; allocation-free) ----------------
__device__ float g_pf    [(size_t)B_*NPTS*C_];
__device__ float g_hid   [(size_t)B_*NPTS*C_];   // xT scratch
__device__ float g_coords[(size_t)B_*NPTS*2];
__device__ float g_score [(size_t)B_*NPTS];
__device__ int   g_top16 [B_*NCAND];
__device__ float g_exsc  [B_*NCAND];
__device__ int   g_topidx[B_*TOPK_];
__device__ float g_mem   [(size_t)B_*10*C_];
__device__ float g_tgt   [(size_t)B_*T_*C_];
__device__ float g_tmp   [(size_t)B_*T_*C_];
__device__ float g_qkv   [(size_t)B_*T_*3*C_];
__device__ float g_attn  [(size_t)B_*T_*C_];
__device__ float g_ffh   [(size_t)B_*T_*FF_];
__device__ float g_memkv [(size_t)B_*10*2*C_];
__device__ float g_q     [(size_t)B_*T_*C_];

// ---------------- tf32 mma ----------------
__device__ __forceinline__ void mma8(float* d, const float* a, const float* b){
    asm volatile("mma.sync.aligned.m16n8k8.row.col.f32.tf32.tf32.f32 "
        "{%0,%1,%2,%3},{%4,%5,%6,%7},{%8,%9},{%0,%1,%2,%3};\n"
        : "+f"(d[0]), "+f"(d[1]), "+f"(d[2]), "+f"(d[3])
        : "r"(__float_as_uint(a[0])), "r"(__float_as_uint(a[1])),
          "r"(__float_as_uint(a[2])), "r"(__float_as_uint(a[3])),
          "r"(__float_as_uint(b[0])), "r"(__float_as_uint(b[1])));
}

// ---------------- TF32 MMA GEMM (NN, cp.async 4-stage pipeline) ----------------
// A row-major staged at stride 20 floats (conflict-free frag loads),
// B row-major staged at stride 136 floats. k-step 16, 4 stages in smem.
// SCORE mode: bias+relu, dot with w2[c], row-reduce, atomicAdd into score.
#define GA_STRIDE 20
#define GB_STRIDE 136
#define GSTAGE_F  (128*GA_STRIDE + 16*GB_STRIDE)   // 4736 floats
#define GSMEM_B   (4 * GSTAGE_F * 4)               // 75776 bytes

template<bool RELU, bool SCORE>
__global__ __launch_bounds__(256, 2)
void mma_gemm_kernel(const float* __restrict__ A, const float* __restrict__ B,
                     const float* __restrict__ bias, float* __restrict__ C,
                     const float* __restrict__ w2, float* __restrict__ score,
                     int M, int N, int K, int lda, int ldb, int ldc,
                     long sA1, long sA2, long sB1, long sB2, long sC1, long sC2,
                     float scale)
{
    extern __shared__ float smem[];

    int z = blockIdx.z, zb = z >> 3, zh = z & 7;
    A += (size_t)zb * sA1 + (size_t)zh * sA2;
    B += (size_t)zb * sB1 + (size_t)zh * sB2;
    if (!SCORE) C += (size_t)zb * sC1 + (size_t)zh * sC2;

    int tid = threadIdx.x, lane = tid & 31, warp = tid >> 5;
    int gid = lane >> 2, tig = lane & 3;
    int wm = warp >> 2, wn = warp & 3;
    int row0 = blockIdx.y * 128, col0 = blockIdx.x * 128;

    float acc[4][4][4];
    #pragma unroll
    for (int i = 0; i < 4; i++)
        #pragma unroll
        for (int j = 0; j < 4; j++)
            #pragma unroll
            for (int r = 0; r < 4; r++) acc[i][j][r] = 0.f;

    // per-thread constant copy coords
    int arow0 = tid >> 2,        aseg0 = tid & 3;          // + 0
    int arow1 = (tid + 256) >> 2,aseg1 = tid & 3;          // + 256
    int ss0 = (row0 + arow0 < M) ? 16 : 0;
    int ss1 = (row0 + arow1 < M) ? 16 : 0;
    int car0 = (ss0 ? row0 + arow0 : 0);
    int car1 = (ss1 ? row0 + arow1 : 0);
    int brow0 = tid >> 5,         bseg0 = tid & 31;
    int brow1 = (tid + 256) >> 5, bseg1 = tid & 31;

    auto issue_stage = [&](int stage, int k0){
        float* Ab = smem + stage*GSTAGE_F;
        float* Bb = Ab + 128*GA_STRIDE;
        const float* gA0 = A + (size_t)car0*lda + k0 + aseg0*4;
        uint32_t dA0 = (uint32_t)__cvta_generic_to_shared(Ab + arow0*GA_STRIDE + aseg0*4);
        asm volatile("cp.async.cg.shared.global [%0], [%1], 16, %2;\n" :: "r"(dA0), "l"(gA0), "r"(ss0));
        const float* gA1 = A + (size_t)car1*lda + k0 + aseg1*4;
        uint32_t dA1 = (uint32_t)__cvta_generic_to_shared(Ab + arow1*GA_STRIDE + aseg1*4);
        asm volatile("cp.async.cg.shared.global [%0], [%1], 16, %2;\n" :: "r"(dA1), "l"(gA1), "r"(ss1));
        const float* gB0 = B + (size_t)(k0 + brow0)*ldb + col0 + bseg0*4;
        uint32_t dB0 = (uint32_t)__cvta_generic_to_shared(Bb + brow0*GB_STRIDE + bseg0*4);
        asm volatile("cp.async.cg.shared.global [%0], [%1], 16;\n" :: "r"(dB0), "l"(gB0));
        const float* gB1 = B + (size_t)(k0 + brow1)*ldb + col0 + bseg1*4;
        uint32_t dB1 = (uint32_t)__cvta_generic_to_shared(Bb + brow1*GB_STRIDE + bseg1*4);
        asm volatile("cp.async.cg.shared.global [%0], [%1], 16;\n" :: "r"(dB1), "l"(gB1));
    };

    auto compute = [&](int stage){
        const float* As = smem + stage*GSTAGE_F;
        const float* Bs = As + 128*GA_STRIDE;
        #pragma unroll
        for (int kk = 0; kk < 16; kk += 8){
            float ah[4][4], bh[4][2];
            #pragma unroll
            for (int ma = 0; ma < 4; ma++){
                int m = wm*64 + ma*16 + gid;
                const float* r0p = As + (size_t)m*GA_STRIDE + kk + tig;
                const float* r1p = As + (size_t)(m + 8)*GA_STRIDE + kk + tig;
                ah[ma][0] = r0p[0]; ah[ma][1] = r1p[0];
                ah[ma][2] = r0p[4]; ah[ma][3] = r1p[4];
            }
            int k1 = (kk + tig)*GB_STRIDE, k2 = (kk + tig + 4)*GB_STRIDE;
            #pragma unroll
            for (int na = 0; na < 4; na++){
                int n = wn*32 + na*8 + gid;
                bh[na][0] = Bs[k1 + n]; bh[na][1] = Bs[k2 + n];
            }
            #pragma unroll
            for (int ma = 0; ma < 4; ma++)
                #pragma unroll
                for (int na = 0; na < 4; na++)
                    mma8(acc[ma][na], ah[ma], bh[na]);
        }
    };

    int nk = K / 16;
    // prologue: 3 stages in flight
    #pragma unroll
    for (int s = 0; s < 3; s++){
        issue_stage(s, s*16);
        asm volatile("cp.async.commit_group;\n" ::: "memory");
    }
    for (int it = 0; it < nk; it++){
        asm volatile("cp.async.wait_group 2;\n" ::: "memory");
        __syncthreads();
        compute(it & 3);
        int nxt = it + 3;
        if (nxt < nk) issue_stage(nxt & 3, nxt*16);
        asm volatile("cp.async.commit_group;\n" ::: "memory");
    }

    #pragma unroll
    for (int ma = 0; ma < 4; ma++){
        int r0 = row0 + wm*64 + ma*16 + gid;
        float s0 = 0.f, s1 = 0.f;
        #pragma unroll
        for (int na = 0; na < 4; na++){
            int c = col0 + wn*32 + na*8 + 2*tig;
            if (c >= N) continue;
            float b0 = bias ? bias[c] : 0.f;
            float b1 = bias ? bias[c+1] : 0.f;
            float x0 = acc[ma][na][0]*scale + b0;
            float x1 = acc[ma][na][1]*scale + b1;
            float x2 = acc[ma][na][2]*scale + b0;
            float x3 = acc[ma][na][3]*scale + b1;
            if (RELU || SCORE){
                x0 = fmaxf(x0, 0.f); x1 = fmaxf(x1, 0.f);
                x2 = fmaxf(x2, 0.f); x3 = fmaxf(x3, 0.f);
            }
            if (SCORE){
                float w0 = w2[c], w1 = w2[c+1];
                s0 += x0*w0 + x1*w1;
                s1 += x2*w0 + x3*w1;
            } else {
                if (r0 < M){ float2 o = make_float2(x0, x1); *(float2*)&C[(size_t)r0*ldc + c] = o; }
                if (r0 + 8 < M){ float2 o = make_float2(x2, x3); *(float2*)&C[(size_t)(r0+8)*ldc + c] = o; }
            }
        }
        if (SCORE){
            s0 += __shfl_xor_sync(0xffffffffu, s0, 1);
            s0 += __shfl_xor_sync(0xffffffffu, s0, 2);
            s1 += __shfl_xor_sync(0xffffffffu, s1, 1);
            s1 += __shfl_xor_sync(0xffffffffu, s1, 2);
            if (tig == 0){
                if (r0 < M)     atomicAdd(&score[r0], s0);
                if (r0 + 8 < M) atomicAdd(&score[r0 + 8], s1);
            }
        }
    }
}

static void mma_gemm(const float* A, const float* B, const float* bias, float* C,
                     int M, int N, int K, int lda, int ldb, int ldc, int gz,
                     long sA1, long sA2, long sB1, long sB2, long sC1, long sC2,
                     float scale, bool relu){
    dim3 grid((N + 127)/128, (M + 127)/128, gz);
    if (relu){
        cudaFuncSetAttribute(mma_gemm_kernel<true,false>, cudaFuncAttributeMaxDynamicSharedMemorySize, GSMEM_B);
        mma_gemm_kernel<true,false><<<grid,256,GSMEM_B>>>(A,B,bias,C,nullptr,nullptr,M,N,K,lda,ldb,ldc,sA1,sA2,sB1,sB2,sC1,sC2,scale);
    } else {
        cudaFuncSetAttribute(mma_gemm_kernel<false,false>, cudaFuncAttributeMaxDynamicSharedMemorySize, GSMEM_B);
        mma_gemm_kernel<false,false><<<grid,256,GSMEM_B>>>(A,B,bias,C,nullptr,nullptr,M,N,K,lda,ldb,ldc,sA1,sA2,sB1,sB2,sC1,sC2,scale);
    }
}

static void mma_gemm_score(const float* A, const float* B, const float* bias,
                           const float* w2, float* score, int M, int N, int K,
                           int lda, int ldb){
    dim3 grid((N + 127)/128, (M + 127)/128, 1);
    cudaFuncSetAttribute(mma_gemm_kernel<true,true>, cudaFuncAttributeMaxDynamicSharedMemorySize, GSMEM_B);
    mma_gemm_kernel<true,true><<<grid,256,GSMEM_B>>>(A,B,bias,nullptr,w2,score,M,N,K,lda,ldb,0,0,0,0,0,0,0,1.f);
}

// ---------------- flash attention (tf32 MMA, online softmax) ----------------
#define FA_PADK 136
#define FA_PADV 104
#define FA_LOG2E 1.4426950408889634f

__global__ __launch_bounds__(256, 1)
void flash_attn_kernel(const float* __restrict__ qkv, float* __restrict__ out){
    extern __shared__ float sm[];
    float* Ks = sm;
    float* Vs = Ks + 96*FA_PADK;
    float* Ps = Vs + 128*FA_PADV;

    int qt = blockIdx.x, bh = blockIdx.y, b = bh >> 3, h = bh & 7;
    int tid = threadIdx.x, lane = tid & 31, warp = tid >> 5;
    int gid = lane >> 2, tig = lane & 3;
    int m0 = warp * 16;
    int q0 = qt * 128;
    const float iscale = 0.10206207261596577f;

    float qf[12][4];
    {
        const float* Qa = qkv + (size_t)(b*T_ + q0 + m0 + gid)*(3*C_) + h*HD_;
        const float* Qb = Qa + 8*(3*C_);
        #pragma unroll
        for (int kk = 0; kk < 12; kk++){
            qf[kk][0] = Qa[kk*8 + tig]     * iscale;
            qf[kk][1] = Qb[kk*8 + tig]     * iscale;
            qf[kk][2] = Qa[kk*8 + tig + 4] * iscale;
            qf[kk][3] = Qb[kk*8 + tig + 4] * iscale;
        }
    }

    float oacc[12][4];
    #pragma unroll
    for (int i = 0; i < 12; i++)
        #pragma unroll
        for (int j = 0; j < 4; j++) oacc[i][j] = 0.f;
    float mrow0 = -1e30f, mrow1 = -1e30f, lrow0 = 0.f, lrow1 = 0.f;

    for (int kt = 0; kt < 8; kt++){
        __syncthreads();
        {
            const float* Kb = qkv + (size_t)(b*T_ + kt*128)*(3*C_) + C_ + h*HD_;
            const float* Vb = Kb + C_;
            for (int idx = tid; idx < 128*24; idx += 256){
                int r = idx / 24, c4 = idx % 24;
                float4 kv4 = *(const float4*)(Kb + (size_t)r*(3*C_) + c4*4);
                Ks[(c4*4+0)*FA_PADK + r] = kv4.x;
                Ks[(c4*4+1)*FA_PADK + r] = kv4.y;
                Ks[(c4*4+2)*FA_PADK + r] = kv4.z;
                Ks[(c4*4+3)*FA_PADK + r] = kv4.w;
                float4 vv4 = *(const float4*)(Vb + (size_t)r*(3*C_) + c4*4);
                *(float4*)&Vs[r*FA_PADV + c4*4] = vv4;
            }
        }
        __syncthreads();

        float sacc[16][4];
        #pragma unroll
        for (int nf = 0; nf < 16; nf++)
            #pragma unroll
            for (int j = 0; j < 4; j++) sacc[nf][j] = 0.f;
        #pragma unroll
        for (int kk = 0; kk < 12; kk++){
            int k1 = (kk*8 + tig)*FA_PADK, k2 = (kk*8 + tig + 4)*FA_PADK;
            #pragma unroll
            for (int nf = 0; nf < 16; nf++){
                float bfr[2] = { Ks[k1 + nf*8 + gid], Ks[k2 + nf*8 + gid] };
                mma8(sacc[nf], qf[kk], bfr);
            }
        }

        float rm0 = -1e30f, rm1 = -1e30f;
        #pragma unroll
        for (int nf = 0; nf < 16; nf++){
            rm0 = fmaxf(rm0, fmaxf(sacc[nf][0], sacc[nf][1]));
            rm1 = fmaxf(rm1, fmaxf(sacc[nf][2], sacc[nf][3]));
        }
        rm0 = fmaxf(rm0, __shfl_xor_sync(0xffffffffu, rm0, 1));
        rm0 = fmaxf(rm0, __shfl_xor_sync(0xffffffffu, rm0, 2));
        rm1 = fmaxf(rm1, __shfl_xor_sync(0xffffffffu, rm1, 1));
        rm1 = fmaxf(rm1, __shfl_xor_sync(0xffffffffu, rm1, 2));
        float mn0 = fmaxf(mrow0, rm0), mn1 = fmaxf(mrow1, rm1);
        float al0 = exp2f((mrow0 - mn0)*FA_LOG2E);
        float al1 = exp2f((mrow1 - mn1)*FA_LOG2E);
        mrow0 = mn0; mrow1 = mn1;
        float rs0 = 0.f, rs1 = 0.f;
        #pragma unroll
        for (int nf = 0; nf < 16; nf++){
            float p0 = exp2f((sacc[nf][0] - mn0)*FA_LOG2E);
            float p1 = exp2f((sacc[nf][1] - mn0)*FA_LOG2E);
            float p2 = exp2f((sacc[nf][2] - mn1)*FA_LOG2E);
            float p3 = exp2f((sacc[nf][3] - mn1)*FA_LOG2E);
            sacc[nf][0] = p0; sacc[nf][1] = p1; sacc[nf][2] = p2; sacc[nf][3] = p3;
            rs0 += p0 + p1; rs1 += p2 + p3;
        }
        rs0 += __shfl_xor_sync(0xffffffffu, rs0, 1);
        rs0 += __shfl_xor_sync(0xffffffffu, rs0, 2);
        rs1 += __shfl_xor_sync(0xffffffffu, rs1, 1);
        rs1 += __shfl_xor_sync(0xffffffffu, rs1, 2);
        lrow0 = lrow0*al0 + rs0;
        lrow1 = lrow1*al1 + rs1;
        #pragma unroll
        for (int nf = 0; nf < 12; nf++){
            oacc[nf][0] *= al0; oacc[nf][1] *= al0;
            oacc[nf][2] *= al1; oacc[nf][3] *= al1;
        }

        #pragma unroll
        for (int nf = 0; nf < 16; nf++){
            int c = nf*8 + 2*tig;
            Ps[(size_t)c*FA_PADK     + m0 + gid]     = sacc[nf][0];
            Ps[(size_t)(c+1)*FA_PADK + m0 + gid]     = sacc[nf][1];
            Ps[(size_t)c*FA_PADK     + m0 + gid + 8] = sacc[nf][2];
            Ps[(size_t)(c+1)*FA_PADK + m0 + gid + 8] = sacc[nf][3];
        }
        __syncwarp();

        #pragma unroll
        for (int kk = 0; kk < 16; kk++){
            int k1 = (kk*8 + tig)*FA_PADK, k2 = (kk*8 + tig + 4)*FA_PADK;
            float pa[4] = { Ps[k1 + m0 + gid], Ps[k1 + m0 + gid + 8],
                            Ps[k2 + m0 + gid], Ps[k2 + m0 + gid + 8] };
            int v1 = (kk*8 + tig)*FA_PADV, v2 = (kk*8 + tig + 4)*FA_PADV;
            #pragma unroll
            for (int nf = 0; nf < 12; nf++){
                float vb2[2] = { Vs[v1 + nf*8 + gid], Vs[v2 + nf*8 + gid] };
                mma8(oacc[nf], pa, vb2);
            }
        }
    }

    float inv0 = 1.f / lrow0, inv1 = 1.f / lrow1;
    size_t r0 = (size_t)(b*T_ + q0 + m0 + gid);
    #pragma unroll
    for (int nf = 0; nf < 12; nf++){
        int col = h*HD_ + nf*8 + 2*tig;
        float2 o0 = make_float2(oacc[nf][0]*inv0, oacc[nf][1]*inv0);
        float2 o1 = make_float2(oacc[nf][2]*inv1, oacc[nf][3]*inv1);
        *(float2*)&out[r0*C_ + col]       = o0;
        *(float2*)&out[(r0 + 8)*C_ + col] = o1;
    }
}

// ---------------- bilinear helpers ----------------
__device__ __forceinline__ float bilin_img(const float* __restrict__ img, float ix, float iy){
    float x0f = floorf(ix), y0f = floorf(iy);
    int x0 = (int)x0f, y0 = (int)y0f;
    float wx1 = ix - x0f, wy1 = iy - y0f;
    float wx0 = 1.f - wx1, wy0 = 1.f - wy1;
    float v = 0.f;
    bool vx0 = (x0 >= 0) & (x0 < 32);
    bool vx1 = (x0 + 1 >= 0) & (x0 + 1 < 32);
    bool vy0 = (y0 >= 0) & (y0 < 32);
    bool vy1 = (y0 + 1 >= 0) & (y0 + 1 < 32);
    if (vx0 & vy0) v += img[y0*32 + x0]         * wx0 * wy0;
    if (vx1 & vy0) v += img[y0*32 + x0 + 1]     * wx1 * wy0;
    if (vx0 & vy1) v += img[(y0+1)*32 + x0]     * wx0 * wy1;
    if (vx1 & vy1) v += img[(y0+1)*32 + x0 + 1] * wx1 * wy1;
    return v;
}
__device__ __forceinline__ float bilin_pe(const float* __restrict__ pe, float ix, float iy, int c){
    float x0f = floorf(ix), y0f = floorf(iy);
    int x0 = (int)x0f, y0 = (int)y0f;
    float wx1 = ix - x0f, wy1 = iy - y0f;
    float wx0 = 1.f - wx1, wy0 = 1.f - wy1;
    float v = 0.f;
    bool vx0 = (x0 >= 0) & (x0 < 32);
    bool vx1 = (x0 + 1 >= 0) & (x0 + 1 < 32);
    bool vy0 = (y0 >= 0) & (y0 < 32);
    bool vy1 = (y0 + 1 >= 0) & (y0 + 1 < 32);
    if (vx0 & vy0) v += pe[((size_t)(y0*32 + x0))*C_ + c]         * wx0 * wy0;
    if (vx1 & vy0) v += pe[((size_t)(y0*32 + x0 + 1))*C_ + c]     * wx1 * wy0;
    if (vx0 & vy1) v += pe[((size_t)((y0+1)*32 + x0))*C_ + c]     * wx0 * wy1;
    if (vx1 & vy1) v += pe[((size_t)((y0+1)*32 + x0 + 1))*C_ + c] * wx1 * wy1;
    return v;
}

// ---------------- transpose x [B,C,T] -> xT [B,T,C] ----------------
__global__ void transpose_in_kernel(const float* __restrict__ x, float* __restrict__ xT){
    __shared__ float tile[32][33];
    int c0 = blockIdx.x*32, t0 = blockIdx.y*32, b = blockIdx.z;
    for (int i = threadIdx.y; i < 32; i += 8)
        tile[i][threadIdx.x] = x[((size_t)b*C_ + c0 + i)*T_ + t0 + threadIdx.x];
    __syncthreads();
    for (int i = threadIdx.y; i < 32; i += 8)
        xT[((size_t)b*T_ + t0 + i)*C_ + c0 + threadIdx.x] = tile[threadIdx.x][i];
}

// ---------------- blockwise sampling from xT ----------------
__global__ void sample_kernel(const float* __restrict__ xT, const float* __restrict__ brand,
                              float* __restrict__ pf, float* __restrict__ coords){
    int p0 = blockIdx.x * 16;
    __shared__ int   sidx[16][4];
    __shared__ float swt [16][4];
    int tid = threadIdx.x;
    if (tid < 16){
        int bn = p0 + tid;
        int b  = bn >> 11;
        int n  = bn & 2047;
        int k  = n & 1;
        int pw = (n >> 1) & 31;
        int ph = n >> 6;
        const float bs = 0.0625f;
        const float* br = brand + ((((size_t)b*32 + ph)*32 + pw)*2 + k)*2;
        float gx = br[0]*bs + (-1.0f + ph*bs);
        float gy = br[1]*bs + (-1.0f + pw*bs);
        coords[(size_t)bn*2]     = gx;
        coords[(size_t)bn*2 + 1] = gy;
        float ix = ((gx + 1.0f)*32.0f - 1.0f)*0.5f;
        float iy = ((gy + 1.0f)*32.0f - 1.0f)*0.5f;
        float x0f = floorf(ix), y0f = floorf(iy);
        int x0 = (int)x0f, y0 = (int)y0f;
        float wx1 = ix - x0f, wy1 = iy - y0f;
        float wxs[2] = {1.f - wx1, wx1};
        float wys[2] = {1.f - wy1, wy1};
        #pragma unroll
        for (int j = 0; j < 4; j++){
            int xi = x0 + (j & 1), yi = y0 + (j >> 1);
            bool v = (xi >= 0) & (xi < 32) & (yi >= 0) & (yi < 32);
            sidx[tid][j] = v ? (yi*32 + xi) : 0;
            swt [tid][j] = v ? (wxs[j & 1]*wys[j >> 1]) : 0.f;
        }
    }
    __syncthreads();
    int b = (p0 >> 11);
    const float* base = xT + (size_t)b*T_*C_;
    for (int pt = 0; pt < 16; pt++){
        const float* r0 = base + (size_t)sidx[pt][0]*C_;
        const float* r1 = base + (size_t)sidx[pt][1]*C_;
        const float* r2 = base + (size_t)sidx[pt][2]*C_;
        const float* r3 = base + (size_t)sidx[pt][3]*C_;
        float w0 = swt[pt][0], w1 = swt[pt][1], w2 = swt[pt][2], w3 = swt[pt][3];
        float* dst = pf + (size_t)(p0 + pt)*C_;
        for (int c = tid; c < C_; c += 256)
            dst[c] = r0[c]*w0 + r1[c]*w1 + r2[c]*w2 + r3[c]*w3;
    }
}

// ---------------- zero score ----------------
__global__ void zero_score_kernel(float* __restrict__ score){
    int i = blockIdx.x*256 + threadIdx.x;
    if (i < B_*NPTS) score[i] = 0.f;
}

// ---------------- top-K (approx candidates) ----------------
__global__ void topk_kernel(const float* __restrict__ score, int* __restrict__ topidx, int K){
    int b = blockIdx.x;
    __shared__ float sv[2048];
    __shared__ float rv[256];
    __shared__ int   ri[256];
    for (int j = threadIdx.x; j < 2048; j += 256) sv[j] = score[(size_t)b*2048 + j];
    __syncthreads();
    for (int t = 0; t < K; t++){
        float bv = -1e30f; int bi = 0x7fffffff;
        for (int j = threadIdx.x; j < 2048; j += 256){
            float v = sv[j];
            if (v > bv){ bv = v; bi = j; }
        }
        rv[threadIdx.x] = bv; ri[threadIdx.x] = bi;
        __syncthreads();
        for (int s = 128; s; s >>= 1){
            if (threadIdx.x < s){
                float v2 = rv[threadIdx.x + s]; int i2 = ri[threadIdx.x + s];
                if (v2 > rv[threadIdx.x] || (v2 == rv[threadIdx.x] && i2 < ri[threadIdx.x])){
                    rv[threadIdx.x] = v2; ri[threadIdx.x] = i2;
                }
            }
            __syncthreads();
        }
        if (threadIdx.x == 0){
            topidx[b*K + t] = ri[0];
            sv[ri[0]] = -1e30f;
        }
        __syncthreads();
    }
}

// ---------------- exact fp32 rescore of candidates ----------------
__global__ __launch_bounds__(256)
void rescore_kernel(const float* __restrict__ pf, const float* __restrict__ W1,
                    const float* __restrict__ b1, const float* __restrict__ w2,
                    const int* __restrict__ cand, float* __restrict__ exsc){
    int b = blockIdx.x >> 4, c = blockIdx.x & 15;
    int idx = cand[b*NCAND + c];
    __shared__ float spf[C_];
    int tid = threadIdx.x;
    for (int i = tid; i < C_; i += 256) spf[i] = pf[((size_t)b*NPTS + idx)*C_ + i];
    __syncthreads();
    float a0 = b1[tid], a1 = b1[tid+256], a2 = b1[tid+512];
    for (int k = 0; k < C_; k++){
        float v = spf[k];
        const float* w = W1 + (size_t)k*C_;
        a0 += v * w[tid];
        a1 += v * w[tid+256];
        a2 += v * w[tid+512];
    }
    float p = fmaxf(a0,0.f)*w2[tid] + fmaxf(a1,0.f)*w2[tid+256] + fmaxf(a2,0.f)*w2[tid+512];
    #pragma unroll
    for (int o = 16; o; o >>= 1) p += __shfl_down_sync(0xffffffffu, p, o);
    __shared__ float red[8];
    if ((tid & 31) == 0) red[tid >> 5] = p;
    __syncthreads();
    if (tid == 0){
        float s = 0.f;
        #pragma unroll
        for (int i = 0; i < 8; i++) s += red[i];
        exsc[b*NCAND + c] = s;
    }
}

// ---------------- final exact top-5 over candidates ----------------
__global__ void final_top5_kernel(const float* __restrict__ exsc, const int* __restrict__ cand,
                                  int* __restrict__ topidx){
    int b = blockIdx.x;
    if (threadIdx.x == 0){
        float s[NCAND]; int id[NCAND];
        for (int i = 0; i < NCAND; i++){ s[i] = exsc[b*NCAND + i]; id[i] = cand[b*NCAND + i]; }
        for (int t = 0; t < TOPK_; t++){
            int bi = 0;
            float bv = -1e30f; int bid = 0x7fffffff;
            for (int i = 0; i < NCAND; i++){
                if (s[i] > bv || (s[i] == bv && id[i] < bid)){ bv = s[i]; bid = id[i]; bi = i; }
            }
            topidx[b*TOPK_ + t] = id[bi];
            s[bi] = -1e30f;
        }
    }
}

// ---------------- soft_align ----------------
__global__ void soft_align_kernel(const float* __restrict__ mainx, const float* __restrict__ pe,
                                  const float* __restrict__ arand, const float* __restrict__ mqrow,
                                  const float* __restrict__ pf, const float* __restrict__ coords,
                                  const int* __restrict__ topidx, float* __restrict__ memo, int rowBase){
    int b  = blockIdx.x / TOPK_;
    int nk = blockIdx.x % TOPK_;
    int idx = topidx[b*TOPK_ + nk];
    float px = coords[((size_t)b*NPTS + idx)*2 + 0];
    float py = coords[((size_t)b*NPTS + idx)*2 + 1];
    __shared__ float semb[AROUND_*C_];
    __shared__ float red[256];
    __shared__ float res[11];
    __shared__ float sw[AROUND_];
    float ixs[AROUND_], iys[AROUND_];
    #pragma unroll
    for (int a = 0; a < AROUND_; a++){
        const float* ar = arand + (((size_t)b*AROUND_ + a)*TOPK_ + nk)*2;
        float g0 = px + (ar[0]*2.f - 0.5f)*0.2f;
        float g1 = py + (ar[1]*2.f - 0.5f)*0.2f;
        g0 = fminf(fmaxf(g0, -1.f), 1.f);
        g1 = fminf(fmaxf(g1, -1.f), 1.f);
        ixs[a] = ((g0 + 1.f)*32.f - 1.f)*0.5f;
        iys[a] = ((g1 + 1.f)*32.f - 1.f)*0.5f;
    }
    const float* pfrow = pf + ((size_t)b*NPTS + idx)*C_;
    float rep2 = 0.f, num[AROUND_], af2[AROUND_];
    #pragma unroll
    for (int a = 0; a < AROUND_; a++){ num[a] = 0.f; af2[a] = 0.f; }
    for (int c = threadIdx.x; c < C_; c += 256){
        float r = pfrow[c];
        rep2 += r*r;
        const float* img = mainx + ((size_t)b*C_ + c)*T_;
        #pragma unroll
        for (int a = 0; a < AROUND_; a++){
            float af = bilin_img(img, ixs[a], iys[a]);
            num[a] += r*af;
            af2[a] += af*af;
            semb[a*C_ + c] = bilin_pe(pe, ixs[a], iys[a], c);
        }
    }
    float vals[11];
    vals[0] = rep2;
    #pragma unroll
    for (int a = 0; a < AROUND_; a++){ vals[1+a] = num[a]; vals[6+a] = af2[a]; }
    for (int v = 0; v < 11; v++){
        red[threadIdx.x] = vals[v];
        __syncthreads();
        for (int s = 128; s; s >>= 1){
            if (threadIdx.x < s) red[threadIdx.x] += red[threadIdx.x + s];
            __syncthreads();
        }
        if (threadIdx.x == 0) res[v] = red[0];
        __syncthreads();
    }
    if (threadIdx.x == 0){
        float rn = fmaxf(sqrtf(res[0]), 1e-8f);
        float s[AROUND_]; float mx = -1e30f;
        for (int a = 0; a < AROUND_; a++){
            s[a] = res[1+a] / (rn * fmaxf(sqrtf(res[6+a]), 1e-8f));
            mx = fmaxf(mx, s[a]);
        }
        float ss = 0.f;
        for (int a = 0; a < AROUND_; a++){ s[a] = expf(s[a] - mx); ss += s[a]; }
        for (int a = 0; a < AROUND_; a++) sw[a] = s[a] / ss;
    }
    __syncthreads();
    float w0 = sw[0], w1 = sw[1], w2 = sw[2], w3 = sw[3], w4 = sw[4];
    for (int c = threadIdx.x; c < C_; c += 256){
        float o = pfrow[c] + mqrow[c];
        o += semb[0*C_ + c]*w0 + semb[1*C_ + c]*w1 + semb[2*C_ + c]*w2
           + semb[3*C_ + c]*w3 + semb[4*C_ + c]*w4;
        memo[((size_t)b*10 + rowBase + nk)*C_ + c] = o;
    }
}

// ---------------- tgt init ----------------
__global__ void tgt_init_kernel(const float* __restrict__ mainx, const float* __restrict__ mq,
                                const float* __restrict__ pe, float* __restrict__ tgt){
    __shared__ float tile[32][33];
    int c0 = blockIdx.x*32, t0 = blockIdx.y*32, b = blockIdx.z;
    for (int i = threadIdx.y; i < 32; i += 8)
        tile[i][threadIdx.x] = mainx[((size_t)b*C_ + c0 + i)*T_ + t0 + threadIdx.x];
    __syncthreads();
    for (int i = threadIdx.y; i < 32; i += 8){
        int t = t0 + i, c = c0 + threadIdx.x;
        tgt[((size_t)b*T_ + t)*C_ + c] = tile[threadIdx.x][i] + mq[c] + pe[(size_t)t*C_ + c];
    }
}

// ---------------- cross-attention (10 keys) ----------------
__global__ void ca_attn_kernel(const float* __restrict__ q, const float* __restrict__ kv,
                               float* __restrict__ out){
    int bh = blockIdx.y, b = bh >> 3, h = bh & 7;
    int i = blockIdx.x*256 + threadIdx.x;
    __shared__ float Ks[10][96];
    __shared__ float Vsm[10][96];
    for (int idx = threadIdx.x; idx < 960; idx += 256){
        int j = idx / 96, d = idx % 96;
        Ks[j][d]  = kv[((size_t)b*10 + j)*(2*C_) + h*HD_ + d];
        Vsm[j][d] = kv[((size_t)b*10 + j)*(2*C_) + C_ + h*HD_ + d];
    }
    __syncthreads();
    const float* qr = q + ((size_t)b*T_ + i)*C_ + h*HD_;
    float s[10];
    #pragma unroll
    for (int j = 0; j < 10; j++) s[j] = 0.f;
    for (int d = 0; d < HD_; d++){
        float qd = qr[d];
        #pragma unroll
        for (int j = 0; j < 10; j++) s[j] += qd * Ks[j][d];
    }
    const float scale = 0.10206207261596577f;
    float mx = -1e30f;
    #pragma unroll
    for (int j = 0; j < 10; j++){ s[j] *= scale; mx = fmaxf(mx, s[j]); }
    float sum = 0.f;
    #pragma unroll
    for (int j = 0; j < 10; j++){ s[j] = expf(s[j] - mx); sum += s[j]; }
    float inv = 1.f / sum;
    #pragma unroll
    for (int j = 0; j < 10; j++) s[j] *= inv;
    float* orow = out + ((size_t)b*T_ + i)*C_ + h*HD_;
    for (int d = 0; d < HD_; d++){
        float o = 0.f;
        #pragma unroll
        for (int j = 0; j < 10; j++) o += s[j] * Vsm[j][d];
        orow[d] = o;
    }
}

// ---------------- residual add + layernorm ----------------
__global__ void add_ln_kernel(float* __restrict__ tgt, const float* __restrict__ resid,
                              const float* __restrict__ w, const float* __restrict__ bb){
    int row = blockIdx.x, t = threadIdx.x;
    float* p = tgt + (size_t)row*C_;
    const float* r = resid + (size_t)row*C_;
    float v[3];
    float sum = 0.f;
    #pragma unroll
    for (int i = 0; i < 3; i++){ v[i] = p[t + i*256] + r[t + i*256]; sum += v[i]; }
    __shared__ float red[256];
    red[t] = sum; __syncthreads();
    for (int s = 128; s; s >>= 1){ if (t < s) red[t] += red[t + s]; __syncthreads(); }
    float m = red[0] * (1.f/768.f);
    __syncthreads();
    float s2 = 0.f;
    #pragma unroll
    for (int i = 0; i < 3; i++){ float d = v[i] - m; s2 += d*d; }
    red[t] = s2; __syncthreads();
    for (int s = 128; s; s >>= 1){ if (t < s) red[t] += red[t + s]; __syncthreads(); }
    float var = red[0] * (1.f/768.f);
    float rstd = rsqrtf(var + 1e-5f);
    #pragma unroll
    for (int i = 0; i < 3; i++){
        int c = t + i*256;
        p[c] = (v[i] - m)*rstd*w[c] + bb[c];
    }
}

// ---------------- final transpose ----------------
__global__ void transpose_out_kernel(const float* __restrict__ tgt, float* __restrict__ out){
    __shared__ float tile[32][33];
    int c0 = blockIdx.x*32, t0 = blockIdx.y*32, b = blockIdx.z;
    for (int i = threadIdx.y; i < 32; i += 8)
        tile[i][threadIdx.x] = tgt[((size_t)b*T_ + t0 + i)*C_ + c0 + threadIdx.x];
    __syncthreads();
    for (int i = threadIdx.y; i < 32; i += 8)
        out[((size_t)b*C_ + c0 + i)*T_ + t0 + threadIdx.x] = tile[threadIdx.x][i];
}

// ---------------- launch ----------------
extern "C" void kernel_launch(void* const* d_in, const int* in_sizes, int n_in,
                              void* d_out, int out_size){
    const float* mainx      = (const float*)d_in[0];
    const float* others[2]  = {(const float*)d_in[1], (const float*)d_in[2]};
    const float* pe         = (const float*)d_in[3];
    const float* mq         = (const float*)d_in[4];
    const float* s_w1       = (const float*)d_in[5];
    const float* s_b1       = (const float*)d_in[6];
    const float* s_w2       = (const float*)d_in[7];
    const float* s_b2       = (const float*)d_in[8];
    const float* sa_in_w    = (const float*)d_in[9];
    const float* sa_in_b    = (const float*)d_in[10];
    const float* sa_out_w   = (const float*)d_in[11];
    const float* sa_out_b   = (const float*)d_in[12];
    const float* ca_in_w    = (const float*)d_in[13];
    const float* ca_in_b    = (const float*)d_in[14];
    const float* ca_out_w   = (const float*)d_in[15];
    const float* ca_out_b   = (const float*)d_in[16];
    const float* ff1_w      = (const float*)d_in[17];
    const float* ff1_b      = (const float*)d_in[18];
    const float* ff2_w      = (const float*)d_in[19];
    const float* ff2_b      = (const float*)d_in[20];
    const float* ln_w       = (const float*)d_in[21];
    const float* ln_b       = (const float*)d_in[22];
    const float* block_rand = (const float*)d_in[23];
    const float* around_rand= (const float*)d_in[24];
    float* out = (float*)d_out;

    float *pf, *hid, *coords, *score, *memb, *tgt, *tmp, *qkv, *attn, *ffh, *memkv, *qb, *exsc;
    int *topidx, *top16;
    cudaGetSymbolAddress((void**)&pf,     g_pf);
    cudaGetSymbolAddress((void**)&hid,    g_hid);
    cudaGetSymbolAddress((void**)&coords, g_coords);
    cudaGetSymbolAddress((void**)&score,  g_score);
    cudaGetSymbolAddress((void**)&top16,  g_top16);
    cudaGetSymbolAddress((void**)&exsc,   g_exsc);
    cudaGetSymbolAddress((void**)&topidx, g_topidx);
    cudaGetSymbolAddress((void**)&memb,   g_mem);
    cudaGetSymbolAddress((void**)&tgt,    g_tgt);
    cudaGetSymbolAddress((void**)&tmp,    g_tmp);
    cudaGetSymbolAddress((void**)&qkv,    g_qkv);
    cudaGetSymbolAddress((void**)&attn,   g_attn);
    cudaGetSymbolAddress((void**)&ffh,    g_ffh);
    cudaGetSymbolAddress((void**)&memkv,  g_memkv);
    cudaGetSymbolAddress((void**)&qb,     g_q);

    const int FA_SMEM = (96*FA_PADK + 128*FA_PADV + 128*FA_PADK) * 4;
    cudaFuncSetAttribute(flash_attn_kernel, cudaFuncAttributeMaxDynamicSharedMemorySize, FA_SMEM);

    // ---- phase A: modalities ----
    for (int i = 0; i < 2; i++){
        {
            dim3 g(C_/32, T_/32, B_); dim3 bl(32, 8);
            transpose_in_kernel<<<g, bl>>>(others[i], hid);
        }
        sample_kernel<<<B_*NPTS/16, 256>>>(hid, block_rand + (size_t)i*B_*32*32*2*2, pf, coords);
        zero_score_kernel<<<(B_*NPTS + 255)/256, 256>>>(score);
        mma_gemm_score(pf, s_w1, s_b1, s_w2, score, B_*NPTS, C_, C_, C_, C_);
        topk_kernel<<<B_, 256>>>(score, top16, NCAND);
        rescore_kernel<<<B_*NCAND, 256>>>(pf, s_w1, s_b1, s_w2, top16, exsc);
        final_top5_kernel<<<B_, 32>>>(exsc, top16, topidx);
        soft_align_kernel<<<B_*TOPK_, 256>>>(mainx, pe,
                                             around_rand + (size_t)i*B_*AROUND_*TOPK_*2,
                                             mq + (size_t)(i+1)*C_,
                                             pf, coords, topidx, memb, i*TOPK_);
    }

    // ---- tgt init ----
    {
        dim3 g(C_/32, T_/32, B_); dim3 bl(32, 8);
        tgt_init_kernel<<<g, bl>>>(mainx, mq, pe, tgt);
    }

    // ---- decoder layers ----
    for (int l = 0; l < L_; l++){
        mma_gemm(tgt, sa_in_w + (size_t)l*C_*3*C_, sa_in_b + (size_t)l*3*C_, qkv,
                 B_*T_, 3*C_, C_, C_, 3*C_, 3*C_, 1, 0,0,0,0,0,0, 1.f, false);
        {
            dim3 g(T_/128, B_*NHEAD_);
            flash_attn_kernel<<<g, 256, FA_SMEM>>>(qkv, attn);
        }
        mma_gemm(attn, sa_out_w + (size_t)l*C_*C_, sa_out_b + (size_t)l*C_, tmp,
                 B_*T_, C_, C_, C_, C_, C_, 1, 0,0,0,0,0,0, 1.f, false);
        add_ln_kernel<<<B_*T_, 256>>>(tgt, tmp, ln_w + (size_t)(l*3+0)*C_, ln_b + (size_t)(l*3+0)*C_);

        mma_gemm(tgt, ca_in_w + (size_t)l*C_*3*C_, ca_in_b + (size_t)l*3*C_, qb,
                 B_*T_, C_, C_, C_, 3*C_, C_, 1, 0,0,0,0,0,0, 1.f, false);
        mma_gemm(memb, ca_in_w + (size_t)l*C_*3*C_ + C_, ca_in_b + (size_t)l*3*C_ + C_, memkv,
                 B_*10, 2*C_, C_, C_, 3*C_, 2*C_, 1, 0,0,0,0,0,0, 1.f, false);
        { dim3 g(T_/256, B_*NHEAD_); ca_attn_kernel<<<g, 256>>>(qb, memkv, attn); }
        mma_gemm(attn, ca_out_w + (size_t)l*C_*C_, ca_out_b + (size_t)l*C_, tmp,
                 B_*T_, C_, C_, C_, C_, C_, 1, 0,0,0,0,0,0, 1.f, false);
        add_ln_kernel<<<B_*T_, 256>>>(tgt, tmp, ln_w + (size_t)(l*3+1)*C_, ln_b + (size_t)(l*3+1)*C_);

        mma_gemm(tgt, ff1_w + (size_t)l*C_*FF_, ff1_b + (size_t)l*FF_, ffh,
                 B_*T_, FF_, C_, C_, FF_, FF_, 1, 0,0,0,0,0,0, 1.f, true);
        mma_gemm(ffh, ff2_w + (size_t)l*FF_*C_, ff2_b + (size_t)l*C_, tmp,
                 B_*T_, C_, FF_, FF_, C_, C_, 1, 0,0,0,0,0,0, 1.f, false);
        add_ln_kernel<<<B_*T_, 256>>>(tgt, tmp, ln_w + (size_t)(l*3+2)*C_, ln_b + (size_t)(l*3+2)*C_);
    }

    // ---- output transpose ----
    {
        dim3 g(C_/32, T_/32, B_); dim3 bl(32, 8);
        transpose_out_kernel<<<g, bl>>>(tgt, out);
    }
}

// round 9
// speedup vs baseline: 1.3218x; 1.0224x over previous
#include <cuda_runtime.h>
#include <cuda_bf16.h>
#include <math.h>
#include <stdint.h>

// ---------------- constants ----------------
#define B_   8
#define C_   768
#define H_   32
#define W_   32
#define T_   1024          // H*W
#define L_   2
#define FF_  3072
#define NPTS 2048          // PH*PW*K
#define TOPK_ 5
#define NCAND 16
#define AROUND_ 5
#define NHEAD_ 8
#define HD_  96

// ---------------- scratch (device globals; allocation-free) ----------------
__device__ float g_pf    [(size_t)B_*NPTS*C_];   // modality-0 pf
__device__ float g_hid   [(size_t)B_*NPTS*C_];   // modality-0 xT scratch
__device__ float g_coords[2*(size_t)B_*NPTS*2];
__device__ float g_score [2*(size_t)B_*NPTS];
__device__ int   g_top16 [2*B_*NCAND];
__device__ float g_exsc  [2*B_*NCAND];
__device__ int   g_topidx[2*B_*TOPK_];
__device__ float g_mem   [(size_t)B_*10*C_];
__device__ float g_tgt   [(size_t)B_*T_*C_];
__device__ float g_tmp   [(size_t)B_*T_*C_];
__device__ float g_qkv   [(size_t)B_*T_*3*C_];
__device__ float g_attn  [(size_t)B_*T_*C_];
__device__ float g_ffh   [(size_t)B_*T_*FF_];    // also carved as pf1 + xT1 during phase A
__device__ float g_memkv [(size_t)B_*10*2*C_];
__device__ float g_q     [(size_t)B_*T_*C_];

// ---------------- tf32 mma ----------------
__device__ __forceinline__ void mma8(float* d, const float* a, const float* b){
    asm volatile("mma.sync.aligned.m16n8k8.row.col.f32.tf32.tf32.f32 "
        "{%0,%1,%2,%3},{%4,%5,%6,%7},{%8,%9},{%0,%1,%2,%3};\n"
        : "+f"(d[0]), "+f"(d[1]), "+f"(d[2]), "+f"(d[3])
        : "r"(__float_as_uint(a[0])), "r"(__float_as_uint(a[1])),
          "r"(__float_as_uint(a[2])), "r"(__float_as_uint(a[3])),
          "r"(__float_as_uint(b[0])), "r"(__float_as_uint(b[1])));
}

// ---------------- TF32 MMA GEMM (NN, cp.async 4-stage pipeline) ----------------
#define GA_STRIDE 20
#define GB_STRIDE 136
#define GSTAGE_F  (128*GA_STRIDE + 16*GB_STRIDE)   // 4736 floats
#define GSMEM_B   (4 * GSTAGE_F * 4)               // 75776 bytes

template<bool RELU, bool SCORE>
__global__ __launch_bounds__(256, 2)
void mma_gemm_kernel(const float* __restrict__ A, const float* __restrict__ B,
                     const float* __restrict__ bias, float* __restrict__ C,
                     const float* __restrict__ w2, float* __restrict__ score,
                     int M, int N, int K, int lda, int ldb, int ldc,
                     long sA1, long sA2, long sB1, long sB2, long sC1, long sC2,
                     float scale)
{
    extern __shared__ float smem[];

    int z = blockIdx.z, zb = z >> 3, zh = z & 7;
    A += (size_t)zb * sA1 + (size_t)zh * sA2;
    B += (size_t)zb * sB1 + (size_t)zh * sB2;
    if (!SCORE) C += (size_t)zb * sC1 + (size_t)zh * sC2;

    int tid = threadIdx.x, lane = tid & 31, warp = tid >> 5;
    int gid = lane >> 2, tig = lane & 3;
    int wm = warp >> 2, wn = warp & 3;
    int row0 = blockIdx.y * 128, col0 = blockIdx.x * 128;

    float acc[4][4][4];
    #pragma unroll
    for (int i = 0; i < 4; i++)
        #pragma unroll
        for (int j = 0; j < 4; j++)
            #pragma unroll
            for (int r = 0; r < 4; r++) acc[i][j][r] = 0.f;

    int arow0 = tid >> 2,        aseg0 = tid & 3;
    int arow1 = (tid + 256) >> 2,aseg1 = tid & 3;
    int ss0 = (row0 + arow0 < M) ? 16 : 0;
    int ss1 = (row0 + arow1 < M) ? 16 : 0;
    int car0 = (ss0 ? row0 + arow0 : 0);
    int car1 = (ss1 ? row0 + arow1 : 0);
    int brow0 = tid >> 5,         bseg0 = tid & 31;
    int brow1 = (tid + 256) >> 5, bseg1 = tid & 31;

    auto issue_stage = [&](int stage, int k0){
        float* Ab = smem + stage*GSTAGE_F;
        float* Bb = Ab + 128*GA_STRIDE;
        const float* gA0 = A + (size_t)car0*lda + k0 + aseg0*4;
        uint32_t dA0 = (uint32_t)__cvta_generic_to_shared(Ab + arow0*GA_STRIDE + aseg0*4);
        asm volatile("cp.async.cg.shared.global [%0], [%1], 16, %2;\n" :: "r"(dA0), "l"(gA0), "r"(ss0));
        const float* gA1 = A + (size_t)car1*lda + k0 + aseg1*4;
        uint32_t dA1 = (uint32_t)__cvta_generic_to_shared(Ab + arow1*GA_STRIDE + aseg1*4);
        asm volatile("cp.async.cg.shared.global [%0], [%1], 16, %2;\n" :: "r"(dA1), "l"(gA1), "r"(ss1));
        const float* gB0 = B + (size_t)(k0 + brow0)*ldb + col0 + bseg0*4;
        uint32_t dB0 = (uint32_t)__cvta_generic_to_shared(Bb + brow0*GB_STRIDE + bseg0*4);
        asm volatile("cp.async.cg.shared.global [%0], [%1], 16;\n" :: "r"(dB0), "l"(gB0));
        const float* gB1 = B + (size_t)(k0 + brow1)*ldb + col0 + bseg1*4;
        uint32_t dB1 = (uint32_t)__cvta_generic_to_shared(Bb + brow1*GB_STRIDE + bseg1*4);
        asm volatile("cp.async.cg.shared.global [%0], [%1], 16;\n" :: "r"(dB1), "l"(gB1));
    };

    auto compute = [&](int stage){
        const float* As = smem + stage*GSTAGE_F;
        const float* Bs = As + 128*GA_STRIDE;
        #pragma unroll
        for (int kk = 0; kk < 16; kk += 8){
            float ah[4][4], bh[4][2];
            #pragma unroll
            for (int ma = 0; ma < 4; ma++){
                int m = wm*64 + ma*16 + gid;
                const float* r0p = As + (size_t)m*GA_STRIDE + kk + tig;
                const float* r1p = As + (size_t)(m + 8)*GA_STRIDE + kk + tig;
                ah[ma][0] = r0p[0]; ah[ma][1] = r1p[0];
                ah[ma][2] = r0p[4]; ah[ma][3] = r1p[4];
            }
            int k1 = (kk + tig)*GB_STRIDE, k2 = (kk + tig + 4)*GB_STRIDE;
            #pragma unroll
            for (int na = 0; na < 4; na++){
                int n = wn*32 + na*8 + gid;
                bh[na][0] = Bs[k1 + n]; bh[na][1] = Bs[k2 + n];
            }
            #pragma unroll
            for (int ma = 0; ma < 4; ma++)
                #pragma unroll
                for (int na = 0; na < 4; na++)
                    mma8(acc[ma][na], ah[ma], bh[na]);
        }
    };

    int nk = K / 16;
    #pragma unroll
    for (int s = 0; s < 3; s++){
        issue_stage(s, s*16);
        asm volatile("cp.async.commit_group;\n" ::: "memory");
    }
    for (int it = 0; it < nk; it++){
        asm volatile("cp.async.wait_group 2;\n" ::: "memory");
        __syncthreads();
        int nxt = it + 3;
        if (nxt < nk) issue_stage(nxt & 3, nxt*16);   // prefetch BEFORE compute
        asm volatile("cp.async.commit_group;\n" ::: "memory");
        compute(it & 3);
    }

    #pragma unroll
    for (int ma = 0; ma < 4; ma++){
        int r0 = row0 + wm*64 + ma*16 + gid;
        float s0 = 0.f, s1 = 0.f;
        #pragma unroll
        for (int na = 0; na < 4; na++){
            int c = col0 + wn*32 + na*8 + 2*tig;
            if (c >= N) continue;
            float b0 = bias ? bias[c] : 0.f;
            float b1 = bias ? bias[c+1] : 0.f;
            float x0 = acc[ma][na][0]*scale + b0;
            float x1 = acc[ma][na][1]*scale + b1;
            float x2 = acc[ma][na][2]*scale + b0;
            float x3 = acc[ma][na][3]*scale + b1;
            if (RELU || SCORE){
                x0 = fmaxf(x0, 0.f); x1 = fmaxf(x1, 0.f);
                x2 = fmaxf(x2, 0.f); x3 = fmaxf(x3, 0.f);
            }
            if (SCORE){
                float w0 = w2[c], w1 = w2[c+1];
                s0 += x0*w0 + x1*w1;
                s1 += x2*w0 + x3*w1;
            } else {
                if (r0 < M){ float2 o = make_float2(x0, x1); *(float2*)&C[(size_t)r0*ldc + c] = o; }
                if (r0 + 8 < M){ float2 o = make_float2(x2, x3); *(float2*)&C[(size_t)(r0+8)*ldc + c] = o; }
            }
        }
        if (SCORE){
            s0 += __shfl_xor_sync(0xffffffffu, s0, 1);
            s0 += __shfl_xor_sync(0xffffffffu, s0, 2);
            s1 += __shfl_xor_sync(0xffffffffu, s1, 1);
            s1 += __shfl_xor_sync(0xffffffffu, s1, 2);
            if (tig == 0){
                if (r0 < M)     atomicAdd(&score[r0], s0);
                if (r0 + 8 < M) atomicAdd(&score[r0 + 8], s1);
            }
        }
    }
}

static void mma_gemm(const float* A, const float* B, const float* bias, float* C,
                     int M, int N, int K, int lda, int ldb, int ldc, int gz,
                     long sA1, long sA2, long sB1, long sB2, long sC1, long sC2,
                     float scale, bool relu, cudaStream_t st){
    dim3 grid((N + 127)/128, (M + 127)/128, gz);
    if (relu){
        cudaFuncSetAttribute(mma_gemm_kernel<true,false>, cudaFuncAttributeMaxDynamicSharedMemorySize, GSMEM_B);
        mma_gemm_kernel<true,false><<<grid,256,GSMEM_B,st>>>(A,B,bias,C,nullptr,nullptr,M,N,K,lda,ldb,ldc,sA1,sA2,sB1,sB2,sC1,sC2,scale);
    } else {
        cudaFuncSetAttribute(mma_gemm_kernel<false,false>, cudaFuncAttributeMaxDynamicSharedMemorySize, GSMEM_B);
        mma_gemm_kernel<false,false><<<grid,256,GSMEM_B,st>>>(A,B,bias,C,nullptr,nullptr,M,N,K,lda,ldb,ldc,sA1,sA2,sB1,sB2,sC1,sC2,scale);
    }
}

static void mma_gemm_score(const float* A, const float* B, const float* bias,
                           const float* w2, float* score, int M, int N, int K,
                           int lda, int ldb, cudaStream_t st){
    dim3 grid((N + 127)/128, (M + 127)/128, 1);
    cudaFuncSetAttribute(mma_gemm_kernel<true,true>, cudaFuncAttributeMaxDynamicSharedMemorySize, GSMEM_B);
    mma_gemm_kernel<true,true><<<grid,256,GSMEM_B,st>>>(A,B,bias,nullptr,w2,score,M,N,K,lda,ldb,0,0,0,0,0,0,0,1.f);
}

// ---------------- flash attention (tf32 MMA, online softmax) ----------------
#define FA_PADK 136
#define FA_PADV 104
#define FA_LOG2E 1.4426950408889634f

__global__ __launch_bounds__(256, 1)
void flash_attn_kernel(const float* __restrict__ qkv, float* __restrict__ out){
    extern __shared__ float sm[];
    float* Ks = sm;
    float* Vs = Ks + 96*FA_PADK;
    float* Ps = Vs + 128*FA_PADV;

    int qt = blockIdx.x, bh = blockIdx.y, b = bh >> 3, h = bh & 7;
    int tid = threadIdx.x, lane = tid & 31, warp = tid >> 5;
    int gid = lane >> 2, tig = lane & 3;
    int m0 = warp * 16;
    int q0 = qt * 128;
    const float iscale = 0.10206207261596577f;

    float qf[12][4];
    {
        const float* Qa = qkv + (size_t)(b*T_ + q0 + m0 + gid)*(3*C_) + h*HD_;
        const float* Qb = Qa + 8*(3*C_);
        #pragma unroll
        for (int kk = 0; kk < 12; kk++){
            qf[kk][0] = Qa[kk*8 + tig]     * iscale;
            qf[kk][1] = Qb[kk*8 + tig]     * iscale;
            qf[kk][2] = Qa[kk*8 + tig + 4] * iscale;
            qf[kk][3] = Qb[kk*8 + tig + 4] * iscale;
        }
    }

    float oacc[12][4];
    #pragma unroll
    for (int i = 0; i < 12; i++)
        #pragma unroll
        for (int j = 0; j < 4; j++) oacc[i][j] = 0.f;
    float mrow0 = -1e30f, mrow1 = -1e30f, lrow0 = 0.f, lrow1 = 0.f;

    for (int kt = 0; kt < 8; kt++){
        __syncthreads();
        {
            const float* Kb = qkv + (size_t)(b*T_ + kt*128)*(3*C_) + C_ + h*HD_;
            const float* Vb = Kb + C_;
            for (int idx = tid; idx < 128*24; idx += 256){
                int r = idx / 24, c4 = idx % 24;
                float4 kv4 = *(const float4*)(Kb + (size_t)r*(3*C_) + c4*4);
                Ks[(c4*4+0)*FA_PADK + r] = kv4.x;
                Ks[(c4*4+1)*FA_PADK + r] = kv4.y;
                Ks[(c4*4+2)*FA_PADK + r] = kv4.z;
                Ks[(c4*4+3)*FA_PADK + r] = kv4.w;
                float4 vv4 = *(const float4*)(Vb + (size_t)r*(3*C_) + c4*4);
                *(float4*)&Vs[r*FA_PADV + c4*4] = vv4;
            }
        }
        __syncthreads();

        float sacc[16][4];
        #pragma unroll
        for (int nf = 0; nf < 16; nf++)
            #pragma unroll
            for (int j = 0; j < 4; j++) sacc[nf][j] = 0.f;
        #pragma unroll
        for (int kk = 0; kk < 12; kk++){
            int k1 = (kk*8 + tig)*FA_PADK, k2 = (kk*8 + tig + 4)*FA_PADK;
            #pragma unroll
            for (int nf = 0; nf < 16; nf++){
                float bfr[2] = { Ks[k1 + nf*8 + gid], Ks[k2 + nf*8 + gid] };
                mma8(sacc[nf], qf[kk], bfr);
            }
        }

        float rm0 = -1e30f, rm1 = -1e30f;
        #pragma unroll
        for (int nf = 0; nf < 16; nf++){
            rm0 = fmaxf(rm0, fmaxf(sacc[nf][0], sacc[nf][1]));
            rm1 = fmaxf(rm1, fmaxf(sacc[nf][2], sacc[nf][3]));
        }
        rm0 = fmaxf(rm0, __shfl_xor_sync(0xffffffffu, rm0, 1));
        rm0 = fmaxf(rm0, __shfl_xor_sync(0xffffffffu, rm0, 2));
        rm1 = fmaxf(rm1, __shfl_xor_sync(0xffffffffu, rm1, 1));
        rm1 = fmaxf(rm1, __shfl_xor_sync(0xffffffffu, rm1, 2));
        float mn0 = fmaxf(mrow0, rm0), mn1 = fmaxf(mrow1, rm1);
        float al0 = exp2f((mrow0 - mn0)*FA_LOG2E);
        float al1 = exp2f((mrow1 - mn1)*FA_LOG2E);
        mrow0 = mn0; mrow1 = mn1;
        float rs0 = 0.f, rs1 = 0.f;
        #pragma unroll
        for (int nf = 0; nf < 16; nf++){
            float p0 = exp2f((sacc[nf][0] - mn0)*FA_LOG2E);
            float p1 = exp2f((sacc[nf][1] - mn0)*FA_LOG2E);
            float p2 = exp2f((sacc[nf][2] - mn1)*FA_LOG2E);
            float p3 = exp2f((sacc[nf][3] - mn1)*FA_LOG2E);
            sacc[nf][0] = p0; sacc[nf][1] = p1; sacc[nf][2] = p2; sacc[nf][3] = p3;
            rs0 += p0 + p1; rs1 += p2 + p3;
        }
        rs0 += __shfl_xor_sync(0xffffffffu, rs0, 1);
        rs0 += __shfl_xor_sync(0xffffffffu, rs0, 2);
        rs1 += __shfl_xor_sync(0xffffffffu, rs1, 1);
        rs1 += __shfl_xor_sync(0xffffffffu, rs1, 2);
        lrow0 = lrow0*al0 + rs0;
        lrow1 = lrow1*al1 + rs1;
        #pragma unroll
        for (int nf = 0; nf < 12; nf++){
            oacc[nf][0] *= al0; oacc[nf][1] *= al0;
            oacc[nf][2] *= al1; oacc[nf][3] *= al1;
        }

        #pragma unroll
        for (int nf = 0; nf < 16; nf++){
            int c = nf*8 + 2*tig;
            Ps[(size_t)c*FA_PADK     + m0 + gid]     = sacc[nf][0];
            Ps[(size_t)(c+1)*FA_PADK + m0 + gid]     = sacc[nf][1];
            Ps[(size_t)c*FA_PADK     + m0 + gid + 8] = sacc[nf][2];
            Ps[(size_t)(c+1)*FA_PADK + m0 + gid + 8] = sacc[nf][3];
        }
        __syncwarp();

        #pragma unroll
        for (int kk = 0; kk < 16; kk++){
            int k1 = (kk*8 + tig)*FA_PADK, k2 = (kk*8 + tig + 4)*FA_PADK;
            float pa[4] = { Ps[k1 + m0 + gid], Ps[k1 + m0 + gid + 8],
                            Ps[k2 + m0 + gid], Ps[k2 + m0 + gid + 8] };
            int v1 = (kk*8 + tig)*FA_PADV, v2 = (kk*8 + tig + 4)*FA_PADV;
            #pragma unroll
            for (int nf = 0; nf < 12; nf++){
                float vb2[2] = { Vs[v1 + nf*8 + gid], Vs[v2 + nf*8 + gid] };
                mma8(oacc[nf], pa, vb2);
            }
        }
    }

    float inv0 = 1.f / lrow0, inv1 = 1.f / lrow1;
    size_t r0 = (size_t)(b*T_ + q0 + m0 + gid);
    #pragma unroll
    for (int nf = 0; nf < 12; nf++){
        int col = h*HD_ + nf*8 + 2*tig;
        float2 o0 = make_float2(oacc[nf][0]*inv0, oacc[nf][1]*inv0);
        float2 o1 = make_float2(oacc[nf][2]*inv1, oacc[nf][3]*inv1);
        *(float2*)&out[r0*C_ + col]       = o0;
        *(float2*)&out[(r0 + 8)*C_ + col] = o1;
    }
}

// ---------------- bilinear helpers ----------------
__device__ __forceinline__ float bilin_img(const float* __restrict__ img, float ix, float iy){
    float x0f = floorf(ix), y0f = floorf(iy);
    int x0 = (int)x0f, y0 = (int)y0f;
    float wx1 = ix - x0f, wy1 = iy - y0f;
    float wx0 = 1.f - wx1, wy0 = 1.f - wy1;
    float v = 0.f;
    bool vx0 = (x0 >= 0) & (x0 < 32);
    bool vx1 = (x0 + 1 >= 0) & (x0 + 1 < 32);
    bool vy0 = (y0 >= 0) & (y0 < 32);
    bool vy1 = (y0 + 1 >= 0) & (y0 + 1 < 32);
    if (vx0 & vy0) v += img[y0*32 + x0]         * wx0 * wy0;
    if (vx1 & vy0) v += img[y0*32 + x0 + 1]     * wx1 * wy0;
    if (vx0 & vy1) v += img[(y0+1)*32 + x0]     * wx0 * wy1;
    if (vx1 & vy1) v += img[(y0+1)*32 + x0 + 1] * wx1 * wy1;
    return v;
}
__device__ __forceinline__ float bilin_pe(const float* __restrict__ pe, float ix, float iy, int c){
    float x0f = floorf(ix), y0f = floorf(iy);
    int x0 = (int)x0f, y0 = (int)y0f;
    float wx1 = ix - x0f, wy1 = iy - y0f;
    float wx0 = 1.f - wx1, wy0 = 1.f - wy1;
    float v = 0.f;
    bool vx0 = (x0 >= 0) & (x0 < 32);
    bool vx1 = (x0 + 1 >= 0) & (x0 + 1 < 32);
    bool vy0 = (y0 >= 0) & (y0 < 32);
    bool vy1 = (y0 + 1 >= 0) & (y0 + 1 < 32);
    if (vx0 & vy0) v += pe[((size_t)(y0*32 + x0))*C_ + c]         * wx0 * wy0;
    if (vx1 & vy0) v += pe[((size_t)(y0*32 + x0 + 1))*C_ + c]     * wx1 * wy0;
    if (vx0 & vy1) v += pe[((size_t)((y0+1)*32 + x0))*C_ + c]     * wx0 * wy1;
    if (vx1 & vy1) v += pe[((size_t)((y0+1)*32 + x0 + 1))*C_ + c] * wx1 * wy1;
    return v;
}

// ---------------- transpose x [B,C,T] -> xT [B,T,C] ----------------
__global__ void transpose_in_kernel(const float* __restrict__ x, float* __restrict__ xT){
    __shared__ float tile[32][33];
    int c0 = blockIdx.x*32, t0 = blockIdx.y*32, b = blockIdx.z;
    for (int i = threadIdx.y; i < 32; i += 8)
        tile[i][threadIdx.x] = x[((size_t)b*C_ + c0 + i)*T_ + t0 + threadIdx.x];
    __syncthreads();
    for (int i = threadIdx.y; i < 32; i += 8)
        xT[((size_t)b*T_ + t0 + i)*C_ + c0 + threadIdx.x] = tile[threadIdx.x][i];
}

// ---------------- blockwise sampling from xT ----------------
__global__ void sample_kernel(const float* __restrict__ xT, const float* __restrict__ brand,
                              float* __restrict__ pf, float* __restrict__ coords){
    int p0 = blockIdx.x * 16;
    __shared__ int   sidx[16][4];
    __shared__ float swt [16][4];
    int tid = threadIdx.x;
    if (tid < 16){
        int bn = p0 + tid;
        int b  = bn >> 11;
        int n  = bn & 2047;
        int k  = n & 1;
        int pw = (n >> 1) & 31;
        int ph = n >> 6;
        const float bs = 0.0625f;
        const float* br = brand + ((((size_t)b*32 + ph)*32 + pw)*2 + k)*2;
        float gx = br[0]*bs + (-1.0f + ph*bs);
        float gy = br[1]*bs + (-1.0f + pw*bs);
        coords[(size_t)bn*2]     = gx;
        coords[(size_t)bn*2 + 1] = gy;
        float ix = ((gx + 1.0f)*32.0f - 1.0f)*0.5f;
        float iy = ((gy + 1.0f)*32.0f - 1.0f)*0.5f;
        float x0f = floorf(ix), y0f = floorf(iy);
        int x0 = (int)x0f, y0 = (int)y0f;
        float wx1 = ix - x0f, wy1 = iy - y0f;
        float wxs[2] = {1.f - wx1, wx1};
        float wys[2] = {1.f - wy1, wy1};
        #pragma unroll
        for (int j = 0; j < 4; j++){
            int xi = x0 + (j & 1), yi = y0 + (j >> 1);
            bool v = (xi >= 0) & (xi < 32) & (yi >= 0) & (yi < 32);
            sidx[tid][j] = v ? (yi*32 + xi) : 0;
            swt [tid][j] = v ? (wxs[j & 1]*wys[j >> 1]) : 0.f;
        }
    }
    __syncthreads();
    int b = (p0 >> 11);
    const float* base = xT + (size_t)b*T_*C_;
    for (int pt = 0; pt < 16; pt++){
        const float* r0 = base + (size_t)sidx[pt][0]*C_;
        const float* r1 = base + (size_t)sidx[pt][1]*C_;
        const float* r2 = base + (size_t)sidx[pt][2]*C_;
        const float* r3 = base + (size_t)sidx[pt][3]*C_;
        float w0 = swt[pt][0], w1 = swt[pt][1], w2 = swt[pt][2], w3 = swt[pt][3];
        float* dst = pf + (size_t)(p0 + pt)*C_;
        for (int c = tid; c < C_; c += 256)
            dst[c] = r0[c]*w0 + r1[c]*w1 + r2[c]*w2 + r3[c]*w3;
    }
}

// ---------------- zero score ----------------
__global__ void zero_score_kernel(float* __restrict__ score){
    int i = blockIdx.x*256 + threadIdx.x;
    if (i < B_*NPTS) score[i] = 0.f;
}

// ---------------- top-K (approx candidates) ----------------
__global__ void topk_kernel(const float* __restrict__ score, int* __restrict__ topidx, int K){
    int b = blockIdx.x;
    __shared__ float sv[2048];
    __shared__ float rv[256];
    __shared__ int   ri[256];
    for (int j = threadIdx.x; j < 2048; j += 256) sv[j] = score[(size_t)b*2048 + j];
    __syncthreads();
    for (int t = 0; t < K; t++){
        float bv = -1e30f; int bi = 0x7fffffff;
        for (int j = threadIdx.x; j < 2048; j += 256){
            float v = sv[j];
            if (v > bv){ bv = v; bi = j; }
        }
        rv[threadIdx.x] = bv; ri[threadIdx.x] = bi;
        __syncthreads();
        for (int s = 128; s; s >>= 1){
            if (threadIdx.x < s){
                float v2 = rv[threadIdx.x + s]; int i2 = ri[threadIdx.x + s];
                if (v2 > rv[threadIdx.x] || (v2 == rv[threadIdx.x] && i2 < ri[threadIdx.x])){
                    rv[threadIdx.x] = v2; ri[threadIdx.x] = i2;
                }
            }
            __syncthreads();
        }
        if (threadIdx.x == 0){
            topidx[b*K + t] = ri[0];
            sv[ri[0]] = -1e30f;
        }
        __syncthreads();
    }
}

// ---------------- exact fp32 rescore of candidates ----------------
__global__ __launch_bounds__(256)
void rescore_kernel(const float* __restrict__ pf, const float* __restrict__ W1,
                    const float* __restrict__ b1, const float* __restrict__ w2,
                    const int* __restrict__ cand, float* __restrict__ exsc){
    int b = blockIdx.x >> 4, c = blockIdx.x & 15;
    int idx = cand[b*NCAND + c];
    __shared__ float spf[C_];
    int tid = threadIdx.x;
    for (int i = tid; i < C_; i += 256) spf[i] = pf[((size_t)b*NPTS + idx)*C_ + i];
    __syncthreads();
    float a0 = b1[tid], a1 = b1[tid+256], a2 = b1[tid+512];
    for (int k = 0; k < C_; k++){
        float v = spf[k];
        const float* w = W1 + (size_t)k*C_;
        a0 += v * w[tid];
        a1 += v * w[tid+256];
        a2 += v * w[tid+512];
    }
    float p = fmaxf(a0,0.f)*w2[tid] + fmaxf(a1,0.f)*w2[tid+256] + fmaxf(a2,0.f)*w2[tid+512];
    #pragma unroll
    for (int o = 16; o; o >>= 1) p += __shfl_down_sync(0xffffffffu, p, o);
    __shared__ float red[8];
    if ((tid & 31) == 0) red[tid >> 5] = p;
    __syncthreads();
    if (tid == 0){
        float s = 0.f;
        #pragma unroll
        for (int i = 0; i < 8; i++) s += red[i];
        exsc[b*NCAND + c] = s;
    }
}

// ---------------- final exact top-5 over candidates ----------------
__global__ void final_top5_kernel(const float* __restrict__ exsc, const int* __restrict__ cand,
                                  int* __restrict__ topidx){
    int b = blockIdx.x;
    if (threadIdx.x == 0){
        float s[NCAND]; int id[NCAND];
        for (int i = 0; i < NCAND; i++){ s[i] = exsc[b*NCAND + i]; id[i] = cand[b*NCAND + i]; }
        for (int t = 0; t < TOPK_; t++){
            int bi = 0;
            float bv = -1e30f; int bid = 0x7fffffff;
            for (int i = 0; i < NCAND; i++){
                if (s[i] > bv || (s[i] == bv && id[i] < bid)){ bv = s[i]; bid = id[i]; bi = i; }
            }
            topidx[b*TOPK_ + t] = id[bi];
            s[bi] = -1e30f;
        }
    }
}

// ---------------- soft_align ----------------
__global__ void soft_align_kernel(const float* __restrict__ mainx, const float* __restrict__ pe,
                                  const float* __restrict__ arand, const float* __restrict__ mqrow,
                                  const float* __restrict__ pf, const float* __restrict__ coords,
                                  const int* __restrict__ topidx, float* __restrict__ memo, int rowBase){
    int b  = blockIdx.x / TOPK_;
    int nk = blockIdx.x % TOPK_;
    int idx = topidx[b*TOPK_ + nk];
    float px = coords[((size_t)b*NPTS + idx)*2 + 0];
    float py = coords[((size_t)b*NPTS + idx)*2 + 1];
    __shared__ float semb[AROUND_*C_];
    __shared__ float red[256];
    __shared__ float res[11];
    __shared__ float sw[AROUND_];
    float ixs[AROUND_], iys[AROUND_];
    #pragma unroll
    for (int a = 0; a < AROUND_; a++){
        const float* ar = arand + (((size_t)b*AROUND_ + a)*TOPK_ + nk)*2;
        float g0 = px + (ar[0]*2.f - 0.5f)*0.2f;
        float g1 = py + (ar[1]*2.f - 0.5f)*0.2f;
        g0 = fminf(fmaxf(g0, -1.f), 1.f);
        g1 = fminf(fmaxf(g1, -1.f), 1.f);
        ixs[a] = ((g0 + 1.f)*32.f - 1.f)*0.5f;
        iys[a] = ((g1 + 1.f)*32.f - 1.f)*0.5f;
    }
    const float* pfrow = pf + ((size_t)b*NPTS + idx)*C_;
    float rep2 = 0.f, num[AROUND_], af2[AROUND_];
    #pragma unroll
    for (int a = 0; a < AROUND_; a++){ num[a] = 0.f; af2[a] = 0.f; }
    for (int c = threadIdx.x; c < C_; c += 256){
        float r = pfrow[c];
        rep2 += r*r;
        const float* img = mainx + ((size_t)b*C_ + c)*T_;
        #pragma unroll
        for (int a = 0; a < AROUND_; a++){
            float af = bilin_img(img, ixs[a], iys[a]);
            num[a] += r*af;
            af2[a] += af*af;
            semb[a*C_ + c] = bilin_pe(pe, ixs[a], iys[a], c);
        }
    }
    float vals[11];
    vals[0] = rep2;
    #pragma unroll
    for (int a = 0; a < AROUND_; a++){ vals[1+a] = num[a]; vals[6+a] = af2[a]; }
    for (int v = 0; v < 11; v++){
        red[threadIdx.x] = vals[v];
        __syncthreads();
        for (int s = 128; s; s >>= 1){
            if (threadIdx.x < s) red[threadIdx.x] += red[threadIdx.x + s];
            __syncthreads();
        }
        if (threadIdx.x == 0) res[v] = red[0];
        __syncthreads();
    }
    if (threadIdx.x == 0){
        float rn = fmaxf(sqrtf(res[0]), 1e-8f);
        float s[AROUND_]; float mx = -1e30f;
        for (int a = 0; a < AROUND_; a++){
            s[a] = res[1+a] / (rn * fmaxf(sqrtf(res[6+a]), 1e-8f));
            mx = fmaxf(mx, s[a]);
        }
        float ss = 0.f;
        for (int a = 0; a < AROUND_; a++){ s[a] = expf(s[a] - mx); ss += s[a]; }
        for (int a = 0; a < AROUND_; a++) sw[a] = s[a] / ss;
    }
    __syncthreads();
    float w0 = sw[0], w1 = sw[1], w2 = sw[2], w3 = sw[3], w4 = sw[4];
    for (int c = threadIdx.x; c < C_; c += 256){
        float o = pfrow[c] + mqrow[c];
        o += semb[0*C_ + c]*w0 + semb[1*C_ + c]*w1 + semb[2*C_ + c]*w2
           + semb[3*C_ + c]*w3 + semb[4*C_ + c]*w4;
        memo[((size_t)b*10 + rowBase + nk)*C_ + c] = o;
    }
}

// ---------------- tgt init ----------------
__global__ void tgt_init_kernel(const float* __restrict__ mainx, const float* __restrict__ mq,
                                const float* __restrict__ pe, float* __restrict__ tgt){
    __shared__ float tile[32][33];
    int c0 = blockIdx.x*32, t0 = blockIdx.y*32, b = blockIdx.z;
    for (int i = threadIdx.y; i < 32; i += 8)
        tile[i][threadIdx.x] = mainx[((size_t)b*C_ + c0 + i)*T_ + t0 + threadIdx.x];
    __syncthreads();
    for (int i = threadIdx.y; i < 32; i += 8){
        int t = t0 + i, c = c0 + threadIdx.x;
        tgt[((size_t)b*T_ + t)*C_ + c] = tile[threadIdx.x][i] + mq[c] + pe[(size_t)t*C_ + c];
    }
}

// ---------------- cross-attention (10 keys) ----------------
__global__ void ca_attn_kernel(const float* __restrict__ q, const float* __restrict__ kv,
                               float* __restrict__ out){
    int bh = blockIdx.y, b = bh >> 3, h = bh & 7;
    int i = blockIdx.x*256 + threadIdx.x;
    __shared__ float Ks[10][96];
    __shared__ float Vsm[10][96];
    for (int idx = threadIdx.x; idx < 960; idx += 256){
        int j = idx / 96, d = idx % 96;
        Ks[j][d]  = kv[((size_t)b*10 + j)*(2*C_) + h*HD_ + d];
        Vsm[j][d] = kv[((size_t)b*10 + j)*(2*C_) + C_ + h*HD_ + d];
    }
    __syncthreads();
    const float* qr = q + ((size_t)b*T_ + i)*C_ + h*HD_;
    float s[10];
    #pragma unroll
    for (int j = 0; j < 10; j++) s[j] = 0.f;
    for (int d = 0; d < HD_; d++){
        float qd = qr[d];
        #pragma unroll
        for (int j = 0; j < 10; j++) s[j] += qd * Ks[j][d];
    }
    const float scale = 0.10206207261596577f;
    float mx = -1e30f;
    #pragma unroll
    for (int j = 0; j < 10; j++){ s[j] *= scale; mx = fmaxf(mx, s[j]); }
    float sum = 0.f;
    #pragma unroll
    for (int j = 0; j < 10; j++){ s[j] = expf(s[j] - mx); sum += s[j]; }
    float inv = 1.f / sum;
    #pragma unroll
    for (int j = 0; j < 10; j++) s[j] *= inv;
    float* orow = out + ((size_t)b*T_ + i)*C_ + h*HD_;
    for (int d = 0; d < HD_; d++){
        float o = 0.f;
        #pragma unroll
        for (int j = 0; j < 10; j++) o += s[j] * Vsm[j][d];
        orow[d] = o;
    }
}

// ---------------- residual add + layernorm ----------------
__global__ void add_ln_kernel(float* __restrict__ tgt, const float* __restrict__ resid,
                              const float* __restrict__ w, const float* __restrict__ bb){
    int row = blockIdx.x, t = threadIdx.x;
    float* p = tgt + (size_t)row*C_;
    const float* r = resid + (size_t)row*C_;
    float v[3];
    float sum = 0.f;
    #pragma unroll
    for (int i = 0; i < 3; i++){ v[i] = p[t + i*256] + r[t + i*256]; sum += v[i]; }
    __shared__ float red[256];
    red[t] = sum; __syncthreads();
    for (int s = 128; s; s >>= 1){ if (t < s) red[t] += red[t + s]; __syncthreads(); }
    float m = red[0] * (1.f/768.f);
    __syncthreads();
    float s2 = 0.f;
    #pragma unroll
    for (int i = 0; i < 3; i++){ float d = v[i] - m; s2 += d*d; }
    red[t] = s2; __syncthreads();
    for (int s = 128; s; s >>= 1){ if (t < s) red[t] += red[t + s]; __syncthreads(); }
    float var = red[0] * (1.f/768.f);
    float rstd = rsqrtf(var + 1e-5f);
    #pragma unroll
    for (int i = 0; i < 3; i++){
        int c = t + i*256;
        p[c] = (v[i] - m)*rstd*w[c] + bb[c];
    }
}

// ---------------- final transpose ----------------
__global__ void transpose_out_kernel(const float* __restrict__ tgt, float* __restrict__ out){
    __shared__ float tile[32][33];
    int c0 = blockIdx.x*32, t0 = blockIdx.y*32, b = blockIdx.z;
    for (int i = threadIdx.y; i < 32; i += 8)
        tile[i][threadIdx.x] = tgt[((size_t)b*T_ + t0 + i)*C_ + c0 + threadIdx.x];
    __syncthreads();
    for (int i = threadIdx.y; i < 32; i += 8)
        out[((size_t)b*C_ + c0 + i)*T_ + t0 + threadIdx.x] = tile[threadIdx.x][i];
}

// ---------------- launch ----------------
extern "C" void kernel_launch(void* const* d_in, const int* in_sizes, int n_in,
                              void* d_out, int out_size){
    const float* mainx      = (const float*)d_in[0];
    const float* others[2]  = {(const float*)d_in[1], (const float*)d_in[2]};
    const float* pe         = (const float*)d_in[3];
    const float* mq         = (const float*)d_in[4];
    const float* s_w1       = (const float*)d_in[5];
    const float* s_b1       = (const float*)d_in[6];
    const float* s_w2       = (const float*)d_in[7];
    const float* s_b2       = (const float*)d_in[8];
    const float* sa_in_w    = (const float*)d_in[9];
    const float* sa_in_b    = (const float*)d_in[10];
    const float* sa_out_w   = (const float*)d_in[11];
    const float* sa_out_b   = (const float*)d_in[12];
    const float* ca_in_w    = (const float*)d_in[13];
    const float* ca_in_b    = (const float*)d_in[14];
    const float* ca_out_w   = (const float*)d_in[15];
    const float* ca_out_b   = (const float*)d_in[16];
    const float* ff1_w      = (const float*)d_in[17];
    const float* ff1_b      = (const float*)d_in[18];
    const float* ff2_w      = (const float*)d_in[19];
    const float* ff2_b      = (const float*)d_in[20];
    const float* ln_w       = (const float*)d_in[21];
    const float* ln_b       = (const float*)d_in[22];
    const float* block_rand = (const float*)d_in[23];
    const float* around_rand= (const float*)d_in[24];
    float* out = (float*)d_out;

    float *pf0, *hid0, *coords, *score, *memb, *tgt, *tmp, *qkv, *attn, *ffh, *memkv, *qb, *exsc;
    int *topidx, *top16;
    cudaGetSymbolAddress((void**)&pf0,    g_pf);
    cudaGetSymbolAddress((void**)&hid0,   g_hid);
    cudaGetSymbolAddress((void**)&coords, g_coords);
    cudaGetSymbolAddress((void**)&score,  g_score);
    cudaGetSymbolAddress((void**)&top16,  g_top16);
    cudaGetSymbolAddress((void**)&exsc,   g_exsc);
    cudaGetSymbolAddress((void**)&topidx, g_topidx);
    cudaGetSymbolAddress((void**)&memb,   g_mem);
    cudaGetSymbolAddress((void**)&tgt,    g_tgt);
    cudaGetSymbolAddress((void**)&tmp,    g_tmp);
    cudaGetSymbolAddress((void**)&qkv,    g_qkv);
    cudaGetSymbolAddress((void**)&attn,   g_attn);
    cudaGetSymbolAddress((void**)&ffh,    g_ffh);
    cudaGetSymbolAddress((void**)&memkv,  g_memkv);
    cudaGetSymbolAddress((void**)&qb,     g_q);

    // modality-1 scratch carved from ffh (dead until FF1, which is after the join)
    float* pf1  = ffh;
    float* hid1 = ffh + (size_t)B_*NPTS*C_;

    const int FA_SMEM = (96*FA_PADK + 128*FA_PADV + 128*FA_PADK) * 4;
    cudaFuncSetAttribute(flash_attn_kernel, cudaFuncAttributeMaxDynamicSharedMemorySize, FA_SMEM);

    // ---- streams/events: created once on the (uncaptured) correctness call ----
    static cudaStream_t s_m[2] = {nullptr, nullptr};
    static cudaEvent_t  ev_start = nullptr, ev_m[2] = {nullptr, nullptr};
    if (s_m[0] == nullptr){
        cudaStreamCreateWithFlags(&s_m[0], cudaStreamNonBlocking);
        cudaStreamCreateWithFlags(&s_m[1], cudaStreamNonBlocking);
        cudaEventCreateWithFlags(&ev_start, cudaEventDisableTiming);
        cudaEventCreateWithFlags(&ev_m[0], cudaEventDisableTiming);
        cudaEventCreateWithFlags(&ev_m[1], cudaEventDisableTiming);
    }

    // ---- fork: modality pipelines on side streams ----
    cudaEventRecord(ev_start, 0);
    float* pfs[2]     = {pf0, pf1};
    float* hids[2]    = {hid0, hid1};
    for (int i = 0; i < 2; i++){
        cudaStream_t st = s_m[i];
        cudaStreamWaitEvent(st, ev_start, 0);
        float* pf_i  = pfs[i];
        float* hid_i = hids[i];
        float* coords_i = coords + (size_t)i*B_*NPTS*2;
        float* score_i  = score  + (size_t)i*B_*NPTS;
        int*   top16_i  = top16  + i*B_*NCAND;
        float* exsc_i   = exsc   + i*B_*NCAND;
        int*   topidx_i = topidx + i*B_*TOPK_;
        {
            dim3 g(C_/32, T_/32, B_); dim3 bl(32, 8);
            transpose_in_kernel<<<g, bl, 0, st>>>(others[i], hid_i);
        }
        sample_kernel<<<B_*NPTS/16, 256, 0, st>>>(hid_i, block_rand + (size_t)i*B_*32*32*2*2, pf_i, coords_i);
        zero_score_kernel<<<(B_*NPTS + 255)/256, 256, 0, st>>>(score_i);
        mma_gemm_score(pf_i, s_w1, s_b1, s_w2, score_i, B_*NPTS, C_, C_, C_, C_, st);
        topk_kernel<<<B_, 256, 0, st>>>(score_i, top16_i, NCAND);
        rescore_kernel<<<B_*NCAND, 256, 0, st>>>(pf_i, s_w1, s_b1, s_w2, top16_i, exsc_i);
        final_top5_kernel<<<B_, 32, 0, st>>>(exsc_i, top16_i, topidx_i);
        soft_align_kernel<<<B_*TOPK_, 256, 0, st>>>(mainx, pe,
                                                    around_rand + (size_t)i*B_*AROUND_*TOPK_*2,
                                                    mq + (size_t)(i+1)*C_,
                                                    pf_i, coords_i, topidx_i, memb, i*TOPK_);
        cudaEventRecord(ev_m[i], st);
    }

    // ---- decoder prefix on the main stream (independent of phase A) ----
    {
        dim3 g(C_/32, T_/32, B_); dim3 bl(32, 8);
        tgt_init_kernel<<<g, bl>>>(mainx, mq, pe, tgt);
    }
    // layer 0 self-attention block + CA-q (no memb dependency)
    mma_gemm(tgt, sa_in_w, sa_in_b, qkv, B_*T_, 3*C_, C_, C_, 3*C_, 3*C_, 1,
             0,0,0,0,0,0, 1.f, false, 0);
    { dim3 g(T_/128, B_*NHEAD_); flash_attn_kernel<<<g, 256, FA_SMEM>>>(qkv, attn); }
    mma_gemm(attn, sa_out_w, sa_out_b, tmp, B_*T_, C_, C_, C_, C_, C_, 1,
             0,0,0,0,0,0, 1.f, false, 0);
    add_ln_kernel<<<B_*T_, 256>>>(tgt, tmp, ln_w, ln_b);
    mma_gemm(tgt, ca_in_w, ca_in_b, qb, B_*T_, C_, C_, C_, 3*C_, C_, 1,
             0,0,0,0,0,0, 1.f, false, 0);

    // ---- join: memb needed from here on ----
    cudaStreamWaitEvent(0, ev_m[0], 0);
    cudaStreamWaitEvent(0, ev_m[1], 0);

    for (int l = 0; l < L_; l++){
        if (l > 0){
            mma_gemm(tgt, sa_in_w + (size_t)l*C_*3*C_, sa_in_b + (size_t)l*3*C_, qkv,
                     B_*T_, 3*C_, C_, C_, 3*C_, 3*C_, 1, 0,0,0,0,0,0, 1.f, false, 0);
            { dim3 g(T_/128, B_*NHEAD_); flash_attn_kernel<<<g, 256, FA_SMEM>>>(qkv, attn); }
            mma_gemm(attn, sa_out_w + (size_t)l*C_*C_, sa_out_b + (size_t)l*C_, tmp,
                     B_*T_, C_, C_, C_, C_, C_, 1, 0,0,0,0,0,0, 1.f, false, 0);
            add_ln_kernel<<<B_*T_, 256>>>(tgt, tmp, ln_w + (size_t)(l*3+0)*C_, ln_b + (size_t)(l*3+0)*C_);
            mma_gemm(tgt, ca_in_w + (size_t)l*C_*3*C_, ca_in_b + (size_t)l*3*C_, qb,
                     B_*T_, C_, C_, C_, 3*C_, C_, 1, 0,0,0,0,0,0, 1.f, false, 0);
        }
        mma_gemm(memb, ca_in_w + (size_t)l*C_*3*C_ + C_, ca_in_b + (size_t)l*3*C_ + C_, memkv,
                 B_*10, 2*C_, C_, C_, 3*C_, 2*C_, 1, 0,0,0,0,0,0, 1.f, false, 0);
        { dim3 g(T_/256, B_*NHEAD_); ca_attn_kernel<<<g, 256>>>(qb, memkv, attn); }
        mma_gemm(attn, ca_out_w + (size_t)l*C_*C_, ca_out_b + (size_t)l*C_, tmp,
                 B_*T_, C_, C_, C_, C_, C_, 1, 0,0,0,0,0,0, 1.f, false, 0);
        add_ln_kernel<<<B_*T_, 256>>>(tgt, tmp, ln_w + (size_t)(l*3+1)*C_, ln_b + (size_t)(l*3+1)*C_);

        mma_gemm(tgt, ff1_w + (size_t)l*C_*FF_, ff1_b + (size_t)l*FF_, ffh,
                 B_*T_, FF_, C_, C_, FF_, FF_, 1, 0,0,0,0,0,0, 1.f, true, 0);
        mma_gemm(ffh, ff2_w + (size_t)l*FF_*C_, ff2_b + (size_t)l*C_, tmp,
                 B_*T_, C_, FF_, FF_, C_, C_, 1, 0,0,0,0,0,0, 1.f, false, 0);
        add_ln_kernel<<<B_*T_, 256>>>(tgt, tmp, ln_w + (size_t)(l*3+2)*C_, ln_b + (size_t)(l*3+2)*C_);
    }

    // ---- output transpose ----
    {
        dim3 g(C_/32, T_/32, B_); dim3 bl(32, 8);
        transpose_out_kernel<<<g, bl>>>(tgt, out);
    }
}

// round 11
// speedup vs baseline: 1.7256x; 1.3055x over previous
#include <cuda_runtime.h>
#include <cuda_fp16.h>
#include <math.h>
#include <stdint.h>

// ---------------- constants ----------------
#define B_   8
#define C_   768
#define T_   1024
#define L_   2
#define FF_  3072
#define NPTS 2048
#define TOPK_ 5
#define NCAND 16
#define AROUND_ 5
#define NHEAD_ 8
#define HD_  96

// ---------------- scratch ----------------
__device__ float g_pf    [(size_t)B_*NPTS*C_];
__device__ float g_hid   [(size_t)B_*NPTS*C_];
__device__ float g_coords[2*(size_t)B_*NPTS*2];
__device__ float g_score [2*(size_t)B_*NPTS];
__device__ int   g_top16 [2*B_*NCAND];
__device__ float g_exsc  [2*B_*NCAND];
__device__ int   g_topidx[2*B_*TOPK_];
__device__ float g_tgt   [(size_t)B_*T_*C_];
__device__ float g_tmp   [(size_t)B_*T_*C_];
__device__ float g_qkv   [(size_t)B_*T_*3*C_];
__device__ float g_ffh   [(size_t)B_*T_*FF_];      // phase-A scratch: pf1 + xT1
__device__ float g_memkv [(size_t)B_*10*2*C_];
__device__ float g_q     [(size_t)B_*T_*C_];
// fp16 mirrors / weights
__device__ __align__(256) __half g_pf16  [2*(size_t)B_*NPTS*C_];
__device__ __align__(256) __half g_tgt16 [(size_t)B_*T_*C_];
__device__ __align__(256) __half g_attn16[(size_t)B_*T_*C_];
__device__ __align__(256) __half g_memb16[(size_t)B_*10*C_];
__device__ __align__(256) __half g_ffh16 [(size_t)B_*T_*FF_];
__device__ __align__(256) __half g_wt    [19464192];

// ---------------- fp16 mma (m16n8k16) ----------------
__device__ __forceinline__ void mma16(float* d, const uint32_t* a, const uint32_t* b){
    asm volatile("mma.sync.aligned.m16n8k16.row.col.f32.f16.f16.f32 "
        "{%0,%1,%2,%3},{%4,%5,%6,%7},{%8,%9},{%0,%1,%2,%3};\n"
        : "+f"(d[0]), "+f"(d[1]), "+f"(d[2]), "+f"(d[3])
        : "r"(a[0]), "r"(a[1]), "r"(a[2]), "r"(a[3]), "r"(b[0]), "r"(b[1]));
}

// ---------------- fp16 GEMM: C[M,N] = A[M,K] @ WT[N,K]^T + bias ----------------
// MODE 0: fp32 C out. MODE 1: relu, half C16 out. MODE 2: score (relu+dot w2, atomicAdd).
// smem per stage: A 128 rows x 40 halves + B 128 x 40 halves = 20480 B; 4 stages.
#define H_STRIDE_W 20                      // row stride in 32-bit words (= 40 halves)
#define H_STAGE_B  20480
#define H_SMEM_B   (4*H_STAGE_B)

template<int MODE>
__global__ __launch_bounds__(256, 2)
void h_gemm_kernel(const __half* __restrict__ A, const __half* __restrict__ WT,
                   const float* __restrict__ bias, float* __restrict__ C,
                   __half* __restrict__ C16, const float* __restrict__ w2,
                   float* __restrict__ score,
                   int M, int N, int K, int lda, int ldb, int ldc)
{
    extern __shared__ char smraw[];

    int tid = threadIdx.x, lane = tid & 31, warp = tid >> 5;
    int gid = lane >> 2, tig = lane & 3;
    int wm = warp >> 2, wn = warp & 3;
    int row0 = blockIdx.y * 128, col0 = blockIdx.x * 128;

    float acc[4][4][4];
    #pragma unroll
    for (int i = 0; i < 4; i++)
        #pragma unroll
        for (int j = 0; j < 4; j++)
            #pragma unroll
            for (int r = 0; r < 4; r++) acc[i][j][r] = 0.f;

    int r0l = tid >> 2,         seg0 = tid & 3;
    int r1l = (tid + 256) >> 2, seg1 = tid & 3;
    int ss0 = (row0 + r0l < M) ? 16 : 0;
    int ss1 = (row0 + r1l < M) ? 16 : 0;
    int car0 = ss0 ? row0 + r0l : 0;
    int car1 = ss1 ? row0 + r1l : 0;

    auto issue_stage = [&](int stage, int k0){
        char* Ab = smraw + stage*H_STAGE_B;
        char* Bb = Ab + 10240;
        {
            uint32_t d = (uint32_t)__cvta_generic_to_shared(Ab + r0l*80 + seg0*16);
            const __half* s = A + (size_t)car0*lda + k0 + seg0*8;
            asm volatile("cp.async.cg.shared.global [%0], [%1], 16, %2;\n" :: "r"(d), "l"(s), "r"(ss0));
        }
        {
            uint32_t d = (uint32_t)__cvta_generic_to_shared(Ab + r1l*80 + seg1*16);
            const __half* s = A + (size_t)car1*lda + k0 + seg1*8;
            asm volatile("cp.async.cg.shared.global [%0], [%1], 16, %2;\n" :: "r"(d), "l"(s), "r"(ss1));
        }
        {
            uint32_t d = (uint32_t)__cvta_generic_to_shared(Bb + r0l*80 + seg0*16);
            const __half* s = WT + (size_t)(col0 + r0l)*ldb + k0 + seg0*8;
            asm volatile("cp.async.cg.shared.global [%0], [%1], 16;\n" :: "r"(d), "l"(s));
        }
        {
            uint32_t d = (uint32_t)__cvta_generic_to_shared(Bb + r1l*80 + seg1*16);
            const __half* s = WT + (size_t)(col0 + r1l)*ldb + k0 + seg1*8;
            asm volatile("cp.async.cg.shared.global [%0], [%1], 16;\n" :: "r"(d), "l"(s));
        }
        asm volatile("cp.async.commit_group;\n" ::: "memory");
    };

    auto compute = [&](int stage){
        const uint32_t* As = (const uint32_t*)(smraw + stage*H_STAGE_B);
        const uint32_t* Bs = As + 128*H_STRIDE_W;
        #pragma unroll
        for (int kk = 0; kk < 2; kk++){
            int kw = kk*8 + tig;
            uint32_t af[4][4], bf[4][2];
            #pragma unroll
            for (int ma = 0; ma < 4; ma++){
                int m = wm*64 + ma*16 + gid;
                af[ma][0] = As[m*H_STRIDE_W + kw];
                af[ma][1] = As[(m+8)*H_STRIDE_W + kw];
                af[ma][2] = As[m*H_STRIDE_W + kw + 4];
                af[ma][3] = As[(m+8)*H_STRIDE_W + kw + 4];
            }
            #pragma unroll
            for (int na = 0; na < 4; na++){
                int n = wn*32 + na*8 + gid;
                bf[na][0] = Bs[n*H_STRIDE_W + kw];
                bf[na][1] = Bs[n*H_STRIDE_W + kw + 4];
            }
            #pragma unroll
            for (int ma = 0; ma < 4; ma++)
                #pragma unroll
                for (int na = 0; na < 4; na++)
                    mma16(acc[ma][na], af[ma], bf[na]);
        }
    };

    int nc = K / 32;
    #pragma unroll
    for (int s = 0; s < 3; s++) issue_stage(s, s*32);
    for (int it = 0; it < nc; it++){
        asm volatile("cp.async.wait_group 2;\n" ::: "memory");
        __syncthreads();
        int nxt = it + 3;
        if (nxt < nc) issue_stage(nxt & 3, nxt*32);
        else asm volatile("cp.async.commit_group;\n" ::: "memory");
        compute(it & 3);
    }

    #pragma unroll
    for (int ma = 0; ma < 4; ma++){
        int r0 = row0 + wm*64 + ma*16 + gid;
        float s0 = 0.f, s1 = 0.f;
        #pragma unroll
        for (int na = 0; na < 4; na++){
            int c = col0 + wn*32 + na*8 + 2*tig;
            float b0 = bias ? bias[c] : 0.f;
            float b1 = bias ? bias[c+1] : 0.f;
            float x0 = acc[ma][na][0] + b0;
            float x1 = acc[ma][na][1] + b1;
            float x2 = acc[ma][na][2] + b0;
            float x3 = acc[ma][na][3] + b1;
            if (MODE >= 1){
                x0 = fmaxf(x0, 0.f); x1 = fmaxf(x1, 0.f);
                x2 = fmaxf(x2, 0.f); x3 = fmaxf(x3, 0.f);
            }
            if (MODE == 2){
                float w0 = w2[c], w1 = w2[c+1];
                s0 += x0*w0 + x1*w1;
                s1 += x2*w0 + x3*w1;
            } else if (MODE == 1){
                if (r0 < M)     *(__half2*)&C16[(size_t)r0*ldc + c]     = __floats2half2_rn(x0, x1);
                if (r0 + 8 < M) *(__half2*)&C16[(size_t)(r0+8)*ldc + c] = __floats2half2_rn(x2, x3);
            } else {
                if (r0 < M){ float2 o = make_float2(x0, x1); *(float2*)&C[(size_t)r0*ldc + c] = o; }
                if (r0 + 8 < M){ float2 o = make_float2(x2, x3); *(float2*)&C[(size_t)(r0+8)*ldc + c] = o; }
            }
        }
        if (MODE == 2){
            s0 += __shfl_xor_sync(0xffffffffu, s0, 1);
            s0 += __shfl_xor_sync(0xffffffffu, s0, 2);
            s1 += __shfl_xor_sync(0xffffffffu, s1, 1);
            s1 += __shfl_xor_sync(0xffffffffu, s1, 2);
            if (tig == 0){
                if (r0 < M)     atomicAdd(&score[r0], s0);
                if (r0 + 8 < M) atomicAdd(&score[r0 + 8], s1);
            }
        }
    }
}

template<int MODE>
static void h_gemm(const __half* A, const __half* WT, const float* bias, float* C,
                   __half* C16, const float* w2, float* score,
                   int M, int N, int K, int lda, int ldb, int ldc, cudaStream_t st){
    cudaFuncSetAttribute(h_gemm_kernel<MODE>, cudaFuncAttributeMaxDynamicSharedMemorySize, H_SMEM_B);
    dim3 grid(N/128, (M + 127)/128);
    h_gemm_kernel<MODE><<<grid, 256, H_SMEM_B, st>>>(A, WT, bias, C, C16, w2, score, M, N, K, lda, ldb, ldc);
}

// ---------------- weight transpose+convert: W[K][N] fp32 -> WT[N][K] fp16 ----------------
__global__ void transpose_w_kernel(const float* __restrict__ W, __half* __restrict__ WT,
                                   int K, int N){
    __shared__ float tile[32][33];
    int n0 = blockIdx.x*32, k0 = blockIdx.y*32;
    for (int i = threadIdx.y; i < 32; i += 8)
        tile[i][threadIdx.x] = W[(size_t)(k0 + i)*N + n0 + threadIdx.x];
    __syncthreads();
    for (int i = threadIdx.y; i < 32; i += 8)
        WT[(size_t)(n0 + i)*K + k0 + threadIdx.x] = __float2half_rn(tile[threadIdx.x][i]);
}
static void transpose_w(const float* W, __half* WT, int K, int N, cudaStream_t st){
    dim3 g(N/32, K/32); dim3 bl(32, 8);
    transpose_w_kernel<<<g, bl, 0, st>>>(W, WT, K, N);
}

// ---------------- tf32 mma kept for flash attention ----------------
__device__ __forceinline__ void mma8(float* d, const float* a, const float* b){
    asm volatile("mma.sync.aligned.m16n8k8.row.col.f32.tf32.tf32.f32 "
        "{%0,%1,%2,%3},{%4,%5,%6,%7},{%8,%9},{%0,%1,%2,%3};\n"
        : "+f"(d[0]), "+f"(d[1]), "+f"(d[2]), "+f"(d[3])
        : "r"(__float_as_uint(a[0])), "r"(__float_as_uint(a[1])),
          "r"(__float_as_uint(a[2])), "r"(__float_as_uint(a[3])),
          "r"(__float_as_uint(b[0])), "r"(__float_as_uint(b[1])));
}

// ---------------- flash attention (epilogue -> fp16 mirror) ----------------
#define FA_PADK 136
#define FA_PADV 104
#define FA_LOG2E 1.4426950408889634f

__global__ __launch_bounds__(256, 1)
void flash_attn_kernel(const float* __restrict__ qkv, __half* __restrict__ out16){
    extern __shared__ float sm[];
    float* Ks = sm;
    float* Vs = Ks + 96*FA_PADK;
    float* Ps = Vs + 128*FA_PADV;

    int qt = blockIdx.x, bh = blockIdx.y, b = bh >> 3, h = bh & 7;
    int tid = threadIdx.x, lane = tid & 31, warp = tid >> 5;
    int gid = lane >> 2, tig = lane & 3;
    int m0 = warp * 16;
    int q0 = qt * 128;
    const float iscale = 0.10206207261596577f;

    float qf[12][4];
    {
        const float* Qa = qkv + (size_t)(b*T_ + q0 + m0 + gid)*(3*C_) + h*HD_;
        const float* Qb = Qa + 8*(3*C_);
        #pragma unroll
        for (int kk = 0; kk < 12; kk++){
            qf[kk][0] = Qa[kk*8 + tig]     * iscale;
            qf[kk][1] = Qb[kk*8 + tig]     * iscale;
            qf[kk][2] = Qa[kk*8 + tig + 4] * iscale;
            qf[kk][3] = Qb[kk*8 + tig + 4] * iscale;
        }
    }

    float oacc[12][4];
    #pragma unroll
    for (int i = 0; i < 12; i++)
        #pragma unroll
        for (int j = 0; j < 4; j++) oacc[i][j] = 0.f;
    float mrow0 = -1e30f, mrow1 = -1e30f, lrow0 = 0.f, lrow1 = 0.f;

    for (int kt = 0; kt < 8; kt++){
        __syncthreads();
        {
            const float* Kb = qkv + (size_t)(b*T_ + kt*128)*(3*C_) + C_ + h*HD_;
            const float* Vb = Kb + C_;
            for (int idx = tid; idx < 128*24; idx += 256){
                int r = idx / 24, c4 = idx % 24;
                float4 kv4 = *(const float4*)(Kb + (size_t)r*(3*C_) + c4*4);
                Ks[(c4*4+0)*FA_PADK + r] = kv4.x;
                Ks[(c4*4+1)*FA_PADK + r] = kv4.y;
                Ks[(c4*4+2)*FA_PADK + r] = kv4.z;
                Ks[(c4*4+3)*FA_PADK + r] = kv4.w;
                float4 vv4 = *(const float4*)(Vb + (size_t)r*(3*C_) + c4*4);
                *(float4*)&Vs[r*FA_PADV + c4*4] = vv4;
            }
        }
        __syncthreads();

        float sacc[16][4];
        #pragma unroll
        for (int nf = 0; nf < 16; nf++)
            #pragma unroll
            for (int j = 0; j < 4; j++) sacc[nf][j] = 0.f;
        #pragma unroll
        for (int kk = 0; kk < 12; kk++){
            int k1 = (kk*8 + tig)*FA_PADK, k2 = (kk*8 + tig + 4)*FA_PADK;
            #pragma unroll
            for (int nf = 0; nf < 16; nf++){
                float bfr[2] = { Ks[k1 + nf*8 + gid], Ks[k2 + nf*8 + gid] };
                mma8(sacc[nf], qf[kk], bfr);
            }
        }

        float rm0 = -1e30f, rm1 = -1e30f;
        #pragma unroll
        for (int nf = 0; nf < 16; nf++){
            rm0 = fmaxf(rm0, fmaxf(sacc[nf][0], sacc[nf][1]));
            rm1 = fmaxf(rm1, fmaxf(sacc[nf][2], sacc[nf][3]));
        }
        rm0 = fmaxf(rm0, __shfl_xor_sync(0xffffffffu, rm0, 1));
        rm0 = fmaxf(rm0, __shfl_xor_sync(0xffffffffu, rm0, 2));
        rm1 = fmaxf(rm1, __shfl_xor_sync(0xffffffffu, rm1, 1));
        rm1 = fmaxf(rm1, __shfl_xor_sync(0xffffffffu, rm1, 2));
        float mn0 = fmaxf(mrow0, rm0), mn1 = fmaxf(mrow1, rm1);
        float al0 = exp2f((mrow0 - mn0)*FA_LOG2E);
        float al1 = exp2f((mrow1 - mn1)*FA_LOG2E);
        mrow0 = mn0; mrow1 = mn1;
        float rs0 = 0.f, rs1 = 0.f;
        #pragma unroll
        for (int nf = 0; nf < 16; nf++){
            float p0 = exp2f((sacc[nf][0] - mn0)*FA_LOG2E);
            float p1 = exp2f((sacc[nf][1] - mn0)*FA_LOG2E);
            float p2 = exp2f((sacc[nf][2] - mn1)*FA_LOG2E);
            float p3 = exp2f((sacc[nf][3] - mn1)*FA_LOG2E);
            sacc[nf][0] = p0; sacc[nf][1] = p1; sacc[nf][2] = p2; sacc[nf][3] = p3;
            rs0 += p0 + p1; rs1 += p2 + p3;
        }
        rs0 += __shfl_xor_sync(0xffffffffu, rs0, 1);
        rs0 += __shfl_xor_sync(0xffffffffu, rs0, 2);
        rs1 += __shfl_xor_sync(0xffffffffu, rs1, 1);
        rs1 += __shfl_xor_sync(0xffffffffu, rs1, 2);
        lrow0 = lrow0*al0 + rs0;
        lrow1 = lrow1*al1 + rs1;
        #pragma unroll
        for (int nf = 0; nf < 12; nf++){
            oacc[nf][0] *= al0; oacc[nf][1] *= al0;
            oacc[nf][2] *= al1; oacc[nf][3] *= al1;
        }

        #pragma unroll
        for (int nf = 0; nf < 16; nf++){
            int c = nf*8 + 2*tig;
            Ps[(size_t)c*FA_PADK     + m0 + gid]     = sacc[nf][0];
            Ps[(size_t)(c+1)*FA_PADK + m0 + gid]     = sacc[nf][1];
            Ps[(size_t)c*FA_PADK     + m0 + gid + 8] = sacc[nf][2];
            Ps[(size_t)(c+1)*FA_PADK + m0 + gid + 8] = sacc[nf][3];
        }
        __syncwarp();

        #pragma unroll
        for (int kk = 0; kk < 16; kk++){
            int k1 = (kk*8 + tig)*FA_PADK, k2 = (kk*8 + tig + 4)*FA_PADK;
            float pa[4] = { Ps[k1 + m0 + gid], Ps[k1 + m0 + gid + 8],
                            Ps[k2 + m0 + gid], Ps[k2 + m0 + gid + 8] };
            int v1 = (kk*8 + tig)*FA_PADV, v2 = (kk*8 + tig + 4)*FA_PADV;
            #pragma unroll
            for (int nf = 0; nf < 12; nf++){
                float vb2[2] = { Vs[v1 + nf*8 + gid], Vs[v2 + nf*8 + gid] };
                mma8(oacc[nf], pa, vb2);
            }
        }
    }

    float inv0 = 1.f / lrow0, inv1 = 1.f / lrow1;
    size_t r0 = (size_t)(b*T_ + q0 + m0 + gid);
    #pragma unroll
    for (int nf = 0; nf < 12; nf++){
        int col = h*HD_ + nf*8 + 2*tig;
        *(__half2*)&out16[r0*C_ + col]       = __floats2half2_rn(oacc[nf][0]*inv0, oacc[nf][1]*inv0);
        *(__half2*)&out16[(r0 + 8)*C_ + col] = __floats2half2_rn(oacc[nf][2]*inv1, oacc[nf][3]*inv1);
    }
}

// ---------------- bilinear helpers ----------------
__device__ __forceinline__ float bilin_img(const float* __restrict__ img, float ix, float iy){
    float x0f = floorf(ix), y0f = floorf(iy);
    int x0 = (int)x0f, y0 = (int)y0f;
    float wx1 = ix - x0f, wy1 = iy - y0f;
    float wx0 = 1.f - wx1, wy0 = 1.f - wy1;
    float v = 0.f;
    bool vx0 = (x0 >= 0) & (x0 < 32);
    bool vx1 = (x0 + 1 >= 0) & (x0 + 1 < 32);
    bool vy0 = (y0 >= 0) & (y0 < 32);
    bool vy1 = (y0 + 1 >= 0) & (y0 + 1 < 32);
    if (vx0 & vy0) v += img[y0*32 + x0]         * wx0 * wy0;
    if (vx1 & vy0) v += img[y0*32 + x0 + 1]     * wx1 * wy0;
    if (vx0 & vy1) v += img[(y0+1)*32 + x0]     * wx0 * wy1;
    if (vx1 & vy1) v += img[(y0+1)*32 + x0 + 1] * wx1 * wy1;
    return v;
}
__device__ __forceinline__ float bilin_pe(const float* __restrict__ pe, float ix, float iy, int c){
    float x0f = floorf(ix), y0f = floorf(iy);
    int x0 = (int)x0f, y0 = (int)y0f;
    float wx1 = ix - x0f, wy1 = iy - y0f;
    float wx0 = 1.f - wx1, wy0 = 1.f - wy1;
    float v = 0.f;
    bool vx0 = (x0 >= 0) & (x0 < 32);
    bool vx1 = (x0 + 1 >= 0) & (x0 + 1 < 32);
    bool vy0 = (y0 >= 0) & (y0 < 32);
    bool vy1 = (y0 + 1 >= 0) & (y0 + 1 < 32);
    if (vx0 & vy0) v += pe[((size_t)(y0*32 + x0))*C_ + c]         * wx0 * wy0;
    if (vx1 & vy0) v += pe[((size_t)(y0*32 + x0 + 1))*C_ + c]     * wx1 * wy0;
    if (vx0 & vy1) v += pe[((size_t)((y0+1)*32 + x0))*C_ + c]     * wx0 * wy1;
    if (vx1 & vy1) v += pe[((size_t)((y0+1)*32 + x0 + 1))*C_ + c] * wx1 * wy1;
    return v;
}

// ---------------- transpose x [B,C,T] -> xT [B,T,C] ----------------
__global__ void transpose_in_kernel(const float* __restrict__ x, float* __restrict__ xT){
    __shared__ float tile[32][33];
    int c0 = blockIdx.x*32, t0 = blockIdx.y*32, b = blockIdx.z;
    for (int i = threadIdx.y; i < 32; i += 8)
        tile[i][threadIdx.x] = x[((size_t)b*C_ + c0 + i)*T_ + t0 + threadIdx.x];
    __syncthreads();
    for (int i = threadIdx.y; i < 32; i += 8)
        xT[((size_t)b*T_ + t0 + i)*C_ + c0 + threadIdx.x] = tile[threadIdx.x][i];
}

// ---------------- blockwise sampling (writes fp32 + fp16) ----------------
__global__ void sample_kernel(const float* __restrict__ xT, const float* __restrict__ brand,
                              float* __restrict__ pf, __half* __restrict__ pf16,
                              float* __restrict__ coords){
    int p0 = blockIdx.x * 16;
    __shared__ int   sidx[16][4];
    __shared__ float swt [16][4];
    int tid = threadIdx.x;
    if (tid < 16){
        int bn = p0 + tid;
        int b  = bn >> 11;
        int n  = bn & 2047;
        int k  = n & 1;
        int pw = (n >> 1) & 31;
        int ph = n >> 6;
        const float bs = 0.0625f;
        const float* br = brand + ((((size_t)b*32 + ph)*32 + pw)*2 + k)*2;
        float gx = br[0]*bs + (-1.0f + ph*bs);
        float gy = br[1]*bs + (-1.0f + pw*bs);
        coords[(size_t)bn*2]     = gx;
        coords[(size_t)bn*2 + 1] = gy;
        float ix = ((gx + 1.0f)*32.0f - 1.0f)*0.5f;
        float iy = ((gy + 1.0f)*32.0f - 1.0f)*0.5f;
        float x0f = floorf(ix), y0f = floorf(iy);
        int x0 = (int)x0f, y0 = (int)y0f;
        float wx1 = ix - x0f, wy1 = iy - y0f;
        float wxs[2] = {1.f - wx1, wx1};
        float wys[2] = {1.f - wy1, wy1};
        #pragma unroll
        for (int j = 0; j < 4; j++){
            int xi = x0 + (j & 1), yi = y0 + (j >> 1);
            bool v = (xi >= 0) & (xi < 32) & (yi >= 0) & (yi < 32);
            sidx[tid][j] = v ? (yi*32 + xi) : 0;
            swt [tid][j] = v ? (wxs[j & 1]*wys[j >> 1]) : 0.f;
        }
    }
    __syncthreads();
    int b = (p0 >> 11);
    const float* base = xT + (size_t)b*T_*C_;
    for (int pt = 0; pt < 16; pt++){
        const float* r0 = base + (size_t)sidx[pt][0]*C_;
        const float* r1 = base + (size_t)sidx[pt][1]*C_;
        const float* r2 = base + (size_t)sidx[pt][2]*C_;
        const float* r3 = base + (size_t)sidx[pt][3]*C_;
        float w0 = swt[pt][0], w1 = swt[pt][1], w2 = swt[pt][2], w3 = swt[pt][3];
        float* dst = pf + (size_t)(p0 + pt)*C_;
        __half* dst16 = pf16 + (size_t)(p0 + pt)*C_;
        for (int c = tid; c < C_; c += 256){
            float v = r0[c]*w0 + r1[c]*w1 + r2[c]*w2 + r3[c]*w3;
            dst[c] = v;
            dst16[c] = __float2half_rn(v);
        }
    }
}

// ---------------- zero score ----------------
__global__ void zero_score_kernel(float* __restrict__ score){
    int i = blockIdx.x*256 + threadIdx.x;
    if (i < B_*NPTS) score[i] = 0.f;
}

// ---------------- top-K ----------------
__global__ void topk_kernel(const float* __restrict__ score, int* __restrict__ topidx, int K){
    int b = blockIdx.x;
    __shared__ float sv[2048];
    __shared__ float rv[256];
    __shared__ int   ri[256];
    for (int j = threadIdx.x; j < 2048; j += 256) sv[j] = score[(size_t)b*2048 + j];
    __syncthreads();
    for (int t = 0; t < K; t++){
        float bv = -1e30f; int bi = 0x7fffffff;
        for (int j = threadIdx.x; j < 2048; j += 256){
            float v = sv[j];
            if (v > bv){ bv = v; bi = j; }
        }
        rv[threadIdx.x] = bv; ri[threadIdx.x] = bi;
        __syncthreads();
        for (int s = 128; s; s >>= 1){
            if (threadIdx.x < s){
                float v2 = rv[threadIdx.x + s]; int i2 = ri[threadIdx.x + s];
                if (v2 > rv[threadIdx.x] || (v2 == rv[threadIdx.x] && i2 < ri[threadIdx.x])){
                    rv[threadIdx.x] = v2; ri[threadIdx.x] = i2;
                }
            }
            __syncthreads();
        }
        if (threadIdx.x == 0){
            topidx[b*K + t] = ri[0];
            sv[ri[0]] = -1e30f;
        }
        __syncthreads();
    }
}

// ---------------- exact fp32 rescore ----------------
__global__ __launch_bounds__(256)
void rescore_kernel(const float* __restrict__ pf, const float* __restrict__ W1,
                    const float* __restrict__ b1, const float* __restrict__ w2,
                    const int* __restrict__ cand, float* __restrict__ exsc){
    int b = blockIdx.x >> 4, c = blockIdx.x & 15;
    int idx = cand[b*NCAND + c];
    __shared__ float spf[C_];
    int tid = threadIdx.x;
    for (int i = tid; i < C_; i += 256) spf[i] = pf[((size_t)b*NPTS + idx)*C_ + i];
    __syncthreads();
    float a0 = b1[tid], a1 = b1[tid+256], a2 = b1[tid+512];
    for (int k = 0; k < C_; k++){
        float v = spf[k];
        const float* w = W1 + (size_t)k*C_;
        a0 += v * w[tid];
        a1 += v * w[tid+256];
        a2 += v * w[tid+512];
    }
    float p = fmaxf(a0,0.f)*w2[tid] + fmaxf(a1,0.f)*w2[tid+256] + fmaxf(a2,0.f)*w2[tid+512];
    #pragma unroll
    for (int o = 16; o; o >>= 1) p += __shfl_down_sync(0xffffffffu, p, o);
    __shared__ float red[8];
    if ((tid & 31) == 0) red[tid >> 5] = p;
    __syncthreads();
    if (tid == 0){
        float s = 0.f;
        #pragma unroll
        for (int i = 0; i < 8; i++) s += red[i];
        exsc[b*NCAND + c] = s;
    }
}

// ---------------- final exact top-5 ----------------
__global__ void final_top5_kernel(const float* __restrict__ exsc, const int* __restrict__ cand,
                                  int* __restrict__ topidx){
    int b = blockIdx.x;
    if (threadIdx.x == 0){
        float s[NCAND]; int id[NCAND];
        for (int i = 0; i < NCAND; i++){ s[i] = exsc[b*NCAND + i]; id[i] = cand[b*NCAND + i]; }
        for (int t = 0; t < TOPK_; t++){
            int bi = 0;
            float bv = -1e30f; int bid = 0x7fffffff;
            for (int i = 0; i < NCAND; i++){
                if (s[i] > bv || (s[i] == bv && id[i] < bid)){ bv = s[i]; bid = id[i]; bi = i; }
            }
            topidx[b*TOPK_ + t] = id[bi];
            s[bi] = -1e30f;
        }
    }
}

// ---------------- soft_align (writes fp16 mem rows) ----------------
__global__ void soft_align_kernel(const float* __restrict__ mainx, const float* __restrict__ pe,
                                  const float* __restrict__ arand, const float* __restrict__ mqrow,
                                  const float* __restrict__ pf, const float* __restrict__ coords,
                                  const int* __restrict__ topidx, __half* __restrict__ memo16, int rowBase){
    int b  = blockIdx.x / TOPK_;
    int nk = blockIdx.x % TOPK_;
    int idx = topidx[b*TOPK_ + nk];
    float px = coords[((size_t)b*NPTS + idx)*2 + 0];
    float py = coords[((size_t)b*NPTS + idx)*2 + 1];
    __shared__ float semb[AROUND_*C_];
    __shared__ float red[256];
    __shared__ float res[11];
    __shared__ float sw[AROUND_];
    float ixs[AROUND_], iys[AROUND_];
    #pragma unroll
    for (int a = 0; a < AROUND_; a++){
        const float* ar = arand + (((size_t)b*AROUND_ + a)*TOPK_ + nk)*2;
        float g0 = px + (ar[0]*2.f - 0.5f)*0.2f;
        float g1 = py + (ar[1]*2.f - 0.5f)*0.2f;
        g0 = fminf(fmaxf(g0, -1.f), 1.f);
        g1 = fminf(fmaxf(g1, -1.f), 1.f);
        ixs[a] = ((g0 + 1.f)*32.f - 1.f)*0.5f;
        iys[a] = ((g1 + 1.f)*32.f - 1.f)*0.5f;
    }
    const float* pfrow = pf + ((size_t)b*NPTS + idx)*C_;
    float rep2 = 0.f, num[AROUND_], af2[AROUND_];
    #pragma unroll
    for (int a = 0; a < AROUND_; a++){ num[a] = 0.f; af2[a] = 0.f; }
    for (int c = threadIdx.x; c < C_; c += 256){
        float r = pfrow[c];
        rep2 += r*r;
        const float* img = mainx + ((size_t)b*C_ + c)*T_;
        #pragma unroll
        for (int a = 0; a < AROUND_; a++){
            float af = bilin_img(img, ixs[a], iys[a]);
            num[a] += r*af;
            af2[a] += af*af;
            semb[a*C_ + c] = bilin_pe(pe, ixs[a], iys[a], c);
        }
    }
    float vals[11];
    vals[0] = rep2;
    #pragma unroll
    for (int a = 0; a < AROUND_; a++){ vals[1+a] = num[a]; vals[6+a] = af2[a]; }
    for (int v = 0; v < 11; v++){
        red[threadIdx.x] = vals[v];
        __syncthreads();
        for (int s = 128; s; s >>= 1){
            if (threadIdx.x < s) red[threadIdx.x] += red[threadIdx.x + s];
            __syncthreads();
        }
        if (threadIdx.x == 0) res[v] = red[0];
        __syncthreads();
    }
    if (threadIdx.x == 0){
        float rn = fmaxf(sqrtf(res[0]), 1e-8f);
        float s[AROUND_]; float mx = -1e30f;
        for (int a = 0; a < AROUND_; a++){
            s[a] = res[1+a] / (rn * fmaxf(sqrtf(res[6+a]), 1e-8f));
            mx = fmaxf(mx, s[a]);
        }
        float ss = 0.f;
        for (int a = 0; a < AROUND_; a++){ s[a] = expf(s[a] - mx); ss += s[a]; }
        for (int a = 0; a < AROUND_; a++) sw[a] = s[a] / ss;
    }
    __syncthreads();
    float w0 = sw[0], w1 = sw[1], w2 = sw[2], w3 = sw[3], w4 = sw[4];
    for (int c = threadIdx.x; c < C_; c += 256){
        float o = pfrow[c] + mqrow[c];
        o += semb[0*C_ + c]*w0 + semb[1*C_ + c]*w1 + semb[2*C_ + c]*w2
           + semb[3*C_ + c]*w3 + semb[4*C_ + c]*w4;
        memo16[((size_t)b*10 + rowBase + nk)*C_ + c] = __float2half_rn(o);
    }
}

// ---------------- tgt init (fp32 + fp16) ----------------
__global__ void tgt_init_kernel(const float* __restrict__ mainx, const float* __restrict__ mq,
                                const float* __restrict__ pe, float* __restrict__ tgt,
                                __half* __restrict__ tgt16){
    __shared__ float tile[32][33];
    int c0 = blockIdx.x*32, t0 = blockIdx.y*32, b = blockIdx.z;
    for (int i = threadIdx.y; i < 32; i += 8)
        tile[i][threadIdx.x] = mainx[((size_t)b*C_ + c0 + i)*T_ + t0 + threadIdx.x];
    __syncthreads();
    for (int i = threadIdx.y; i < 32; i += 8){
        int t = t0 + i, c = c0 + threadIdx.x;
        float v = tile[threadIdx.x][i] + mq[c] + pe[(size_t)t*C_ + c];
        tgt[((size_t)b*T_ + t)*C_ + c] = v;
        tgt16[((size_t)b*T_ + t)*C_ + c] = __float2half_rn(v);
    }
}

// ---------------- cross-attention (10 keys; half out) ----------------
__global__ void ca_attn_kernel(const float* __restrict__ q, const float* __restrict__ kv,
                               __half* __restrict__ out16){
    int bh = blockIdx.y, b = bh >> 3, h = bh & 7;
    int i = blockIdx.x*256 + threadIdx.x;
    __shared__ float Ks[10][96];
    __shared__ float Vsm[10][96];
    for (int idx = threadIdx.x; idx < 960; idx += 256){
        int j = idx / 96, d = idx % 96;
        Ks[j][d]  = kv[((size_t)b*10 + j)*(2*C_) + h*HD_ + d];
        Vsm[j][d] = kv[((size_t)b*10 + j)*(2*C_) + C_ + h*HD_ + d];
    }
    __syncthreads();
    const float* qr = q + ((size_t)b*T_ + i)*C_ + h*HD_;
    float s[10];
    #pragma unroll
    for (int j = 0; j < 10; j++) s[j] = 0.f;
    for (int d = 0; d < HD_; d++){
        float qd = qr[d];
        #pragma unroll
        for (int j = 0; j < 10; j++) s[j] += qd * Ks[j][d];
    }
    const float scale = 0.10206207261596577f;
    float mx = -1e30f;
    #pragma unroll
    for (int j = 0; j < 10; j++){ s[j] *= scale; mx = fmaxf(mx, s[j]); }
    float sum = 0.f;
    #pragma unroll
    for (int j = 0; j < 10; j++){ s[j] = expf(s[j] - mx); sum += s[j]; }
    float inv = 1.f / sum;
    #pragma unroll
    for (int j = 0; j < 10; j++) s[j] *= inv;
    __half* orow = out16 + ((size_t)b*T_ + i)*C_ + h*HD_;
    for (int d = 0; d < HD_; d++){
        float o = 0.f;
        #pragma unroll
        for (int j = 0; j < 10; j++) o += s[j] * Vsm[j][d];
        orow[d] = __float2half_rn(o);
    }
}

// ---------------- residual add + layernorm (fp32 + fp16 out) ----------------
__global__ void add_ln_kernel(float* __restrict__ tgt, __half* __restrict__ tgt16,
                              const float* __restrict__ resid,
                              const float* __restrict__ w, const float* __restrict__ bb){
    int row = blockIdx.x, t = threadIdx.x;
    float* p = tgt + (size_t)row*C_;
    __half* p16 = tgt16 + (size_t)row*C_;
    const float* r = resid + (size_t)row*C_;
    float v[3];
    float sum = 0.f;
    #pragma unroll
    for (int i = 0; i < 3; i++){ v[i] = p[t + i*256] + r[t + i*256]; sum += v[i]; }
    __shared__ float red[256];
    red[t] = sum; __syncthreads();
    for (int s = 128; s; s >>= 1){ if (t < s) red[t] += red[t + s]; __syncthreads(); }
    float m = red[0] * (1.f/768.f);
    __syncthreads();
    float s2 = 0.f;
    #pragma unroll
    for (int i = 0; i < 3; i++){ float d = v[i] - m; s2 += d*d; }
    red[t] = s2; __syncthreads();
    for (int s = 128; s; s >>= 1){ if (t < s) red[t] += red[t + s]; __syncthreads(); }
    float var = red[0] * (1.f/768.f);
    float rstd = rsqrtf(var + 1e-5f);
    #pragma unroll
    for (int i = 0; i < 3; i++){
        int c = t + i*256;
        float o = (v[i] - m)*rstd*w[c] + bb[c];
        p[c] = o;
        p16[c] = __float2half_rn(o);
    }
}

// ---------------- final transpose ----------------
__global__ void transpose_out_kernel(const float* __restrict__ tgt, float* __restrict__ out){
    __shared__ float tile[32][33];
    int c0 = blockIdx.x*32, t0 = blockIdx.y*32, b = blockIdx.z;
    for (int i = threadIdx.y; i < 32; i += 8)
        tile[i][threadIdx.x] = tgt[((size_t)b*T_ + t0 + i)*C_ + c0 + threadIdx.x];
    __syncthreads();
    for (int i = threadIdx.y; i < 32; i += 8)
        out[((size_t)b*C_ + c0 + i)*T_ + t0 + threadIdx.x] = tile[threadIdx.x][i];
}

// ---------------- launch ----------------
extern "C" void kernel_launch(void* const* d_in, const int* in_sizes, int n_in,
                              void* d_out, int out_size){
    const float* mainx      = (const float*)d_in[0];
    const float* others[2]  = {(const float*)d_in[1], (const float*)d_in[2]};
    const float* pe         = (const float*)d_in[3];
    const float* mq         = (const float*)d_in[4];
    const float* s_w1       = (const float*)d_in[5];
    const float* s_b1       = (const float*)d_in[6];
    const float* s_w2       = (const float*)d_in[7];
    const float* s_b2       = (const float*)d_in[8];
    const float* sa_in_w    = (const float*)d_in[9];
    const float* sa_in_b    = (const float*)d_in[10];
    const float* sa_out_w   = (const float*)d_in[11];
    const float* sa_out_b   = (const float*)d_in[12];
    const float* ca_in_w    = (const float*)d_in[13];
    const float* ca_in_b    = (const float*)d_in[14];
    const float* ca_out_w   = (const float*)d_in[15];
    const float* ca_out_b   = (const float*)d_in[16];
    const float* ff1_w      = (const float*)d_in[17];
    const float* ff1_b      = (const float*)d_in[18];
    const float* ff2_w      = (const float*)d_in[19];
    const float* ff2_b      = (const float*)d_in[20];
    const float* ln_w       = (const float*)d_in[21];
    const float* ln_b       = (const float*)d_in[22];
    const float* block_rand = (const float*)d_in[23];
    const float* around_rand= (const float*)d_in[24];
    float* out = (float*)d_out;

    float *pf0, *hid0, *coords, *score, *tgt, *tmp, *qkv, *ffh, *memkv, *qb, *exsc;
    int *topidx, *top16;
    __half *pf16, *tgt16, *attn16, *memb16, *ffh16, *wt;
    cudaGetSymbolAddress((void**)&pf0,    g_pf);
    cudaGetSymbolAddress((void**)&hid0,   g_hid);
    cudaGetSymbolAddress((void**)&coords, g_coords);
    cudaGetSymbolAddress((void**)&score,  g_score);
    cudaGetSymbolAddress((void**)&top16,  g_top16);
    cudaGetSymbolAddress((void**)&exsc,   g_exsc);
    cudaGetSymbolAddress((void**)&topidx, g_topidx);
    cudaGetSymbolAddress((void**)&tgt,    g_tgt);
    cudaGetSymbolAddress((void**)&tmp,    g_tmp);
    cudaGetSymbolAddress((void**)&qkv,    g_qkv);
    cudaGetSymbolAddress((void**)&ffh,    g_ffh);
    cudaGetSymbolAddress((void**)&memkv,  g_memkv);
    cudaGetSymbolAddress((void**)&qb,     g_q);
    cudaGetSymbolAddress((void**)&pf16,   g_pf16);
    cudaGetSymbolAddress((void**)&tgt16,  g_tgt16);
    cudaGetSymbolAddress((void**)&attn16, g_attn16);
    cudaGetSymbolAddress((void**)&memb16, g_memb16);
    cudaGetSymbolAddress((void**)&ffh16,  g_ffh16);
    cudaGetSymbolAddress((void**)&wt,     g_wt);

    size_t o = 0;
    __half* wtS = wt + o; o += (size_t)768*768;
    __half *wtSAin[L_], *wtSAout[L_], *wtCAin[L_], *wtCAout[L_], *wtFF1[L_], *wtFF2[L_];
    for (int l = 0; l < L_; l++){
        wtSAin[l]  = wt + o; o += (size_t)2304*768;
        wtSAout[l] = wt + o; o += (size_t)768*768;
        wtCAin[l]  = wt + o; o += (size_t)2304*768;
        wtCAout[l] = wt + o; o += (size_t)768*768;
        wtFF1[l]   = wt + o; o += (size_t)3072*768;
        wtFF2[l]   = wt + o; o += (size_t)768*3072;
    }

    // modality-1 fp32 scratch carved from ffh (dead: FF now uses ffh16)
    float* pf1  = ffh;
    float* hid1 = ffh + (size_t)B_*NPTS*C_;

    const int FA_SMEM = (96*FA_PADK + 128*FA_PADV + 128*FA_PADK) * 4;
    cudaFuncSetAttribute(flash_attn_kernel, cudaFuncAttributeMaxDynamicSharedMemorySize, FA_SMEM);

    static cudaStream_t s_m[2] = {nullptr, nullptr};
    static cudaEvent_t  ev_start = nullptr, ev_m[2] = {nullptr, nullptr};
    if (s_m[0] == nullptr){
        cudaStreamCreateWithFlags(&s_m[0], cudaStreamNonBlocking);
        cudaStreamCreateWithFlags(&s_m[1], cudaStreamNonBlocking);
        cudaEventCreateWithFlags(&ev_start, cudaEventDisableTiming);
        cudaEventCreateWithFlags(&ev_m[0], cudaEventDisableTiming);
        cudaEventCreateWithFlags(&ev_m[1], cudaEventDisableTiming);
    }

    // scoring weight transpose before fork
    transpose_w(s_w1, wtS, 768, 768, 0);
    cudaEventRecord(ev_start, 0);

    // ---- fork: modality pipelines ----
    float*  pfs[2]   = {pf0, pf1};
    float*  hids[2]  = {hid0, hid1};
    for (int i = 0; i < 2; i++){
        cudaStream_t st = s_m[i];
        cudaStreamWaitEvent(st, ev_start, 0);
        float*  pf_i   = pfs[i];
        __half* pf16_i = pf16 + (size_t)i*B_*NPTS*C_;
        float*  hid_i  = hids[i];
        float* coords_i = coords + (size_t)i*B_*NPTS*2;
        float* score_i  = score  + (size_t)i*B_*NPTS;
        int*   top16_i  = top16  + i*B_*NCAND;
        float* exsc_i   = exsc   + i*B_*NCAND;
        int*   topidx_i = topidx + i*B_*TOPK_;
        {
            dim3 g(C_/32, T_/32, B_); dim3 bl(32, 8);
            transpose_in_kernel<<<g, bl, 0, st>>>(others[i], hid_i);
        }
        sample_kernel<<<B_*NPTS/16, 256, 0, st>>>(hid_i, block_rand + (size_t)i*B_*32*32*2*2,
                                                  pf_i, pf16_i, coords_i);
        zero_score_kernel<<<(B_*NPTS + 255)/256, 256, 0, st>>>(score_i);
        h_gemm<2>(pf16_i, wtS, s_b1, nullptr, nullptr, s_w2, score_i,
                  B_*NPTS, C_, C_, C_, C_, 0, st);
        topk_kernel<<<B_, 256, 0, st>>>(score_i, top16_i, NCAND);
        rescore_kernel<<<B_*NCAND, 256, 0, st>>>(pf_i, s_w1, s_b1, s_w2, top16_i, exsc_i);
        final_top5_kernel<<<B_, 32, 0, st>>>(exsc_i, top16_i, topidx_i);
        soft_align_kernel<<<B_*TOPK_, 256, 0, st>>>(mainx, pe,
                                                    around_rand + (size_t)i*B_*AROUND_*TOPK_*2,
                                                    mq + (size_t)(i+1)*C_,
                                                    pf_i, coords_i, topidx_i, memb16, i*TOPK_);
        cudaEventRecord(ev_m[i], st);
    }

    // ---- decoder weight transposes + prefix on main stream ----
    for (int l = 0; l < L_; l++){
        transpose_w(sa_in_w  + (size_t)l*C_*3*C_, wtSAin[l],  768, 2304, 0);
        transpose_w(sa_out_w + (size_t)l*C_*C_,   wtSAout[l], 768, 768,  0);
        transpose_w(ca_in_w  + (size_t)l*C_*3*C_, wtCAin[l],  768, 2304, 0);
        transpose_w(ca_out_w + (size_t)l*C_*C_,   wtCAout[l], 768, 768,  0);
        transpose_w(ff1_w    + (size_t)l*C_*FF_,  wtFF1[l],   768, 3072, 0);
        transpose_w(ff2_w    + (size_t)l*FF_*C_,  wtFF2[l],   3072, 768, 0);
    }
    {
        dim3 g(C_/32, T_/32, B_); dim3 bl(32, 8);
        tgt_init_kernel<<<g, bl>>>(mainx, mq, pe, tgt, tgt16);
    }
    // layer 0 SA block + CA-q (no memb dependency)
    h_gemm<0>(tgt16, wtSAin[0], sa_in_b, qkv, nullptr, nullptr, nullptr,
              B_*T_, 3*C_, C_, C_, C_, 3*C_, 0);
    { dim3 g(T_/128, B_*NHEAD_); flash_attn_kernel<<<g, 256, FA_SMEM>>>(qkv, attn16); }
    h_gemm<0>(attn16, wtSAout[0], sa_out_b, tmp, nullptr, nullptr, nullptr,
              B_*T_, C_, C_, C_, C_, C_, 0);
    add_ln_kernel<<<B_*T_, 256>>>(tgt, tgt16, tmp, ln_w, ln_b);
    h_gemm<0>(tgt16, wtCAin[0], ca_in_b, qb, nullptr, nullptr, nullptr,
              B_*T_, C_, C_, C_, C_, C_, 0);

    // ---- join ----
    cudaStreamWaitEvent(0, ev_m[0], 0);
    cudaStreamWaitEvent(0, ev_m[1], 0);

    for (int l = 0; l < L_; l++){
        if (l > 0){
            h_gemm<0>(tgt16, wtSAin[l], sa_in_b + (size_t)l*3*C_, qkv, nullptr, nullptr, nullptr,
                      B_*T_, 3*C_, C_, C_, C_, 3*C_, 0);
            { dim3 g(T_/128, B_*NHEAD_); flash_attn_kernel<<<g, 256, FA_SMEM>>>(qkv, attn16); }
            h_gemm<0>(attn16, wtSAout[l], sa_out_b + (size_t)l*C_, tmp, nullptr, nullptr, nullptr,
                      B_*T_, C_, C_, C_, C_, C_, 0);
            add_ln_kernel<<<B_*T_, 256>>>(tgt, tgt16, tmp, ln_w + (size_t)(l*3+0)*C_, ln_b + (size_t)(l*3+0)*C_);
            h_gemm<0>(tgt16, wtCAin[l], ca_in_b + (size_t)l*3*C_, qb, nullptr, nullptr, nullptr,
                      B_*T_, C_, C_, C_, C_, C_, 0);
        }
        h_gemm<0>(memb16, wtCAin[l] + (size_t)768*C_, ca_in_b + (size_t)l*3*C_ + C_, memkv,
                  nullptr, nullptr, nullptr, B_*10, 2*C_, C_, C_, C_, 2*C_, 0);
        { dim3 g(T_/256, B_*NHEAD_); ca_attn_kernel<<<g, 256>>>(qb, memkv, attn16); }
        h_gemm<0>(attn16, wtCAout[l], ca_out_b + (size_t)l*C_, tmp, nullptr, nullptr, nullptr,
                  B_*T_, C_, C_, C_, C_, C_, 0);
        add_ln_kernel<<<B_*T_, 256>>>(tgt, tgt16, tmp, ln_w + (size_t)(l*3+1)*C_, ln_b + (size_t)(l*3+1)*C_);

        h_gemm<1>(tgt16, wtFF1[l], ff1_b + (size_t)l*FF_, nullptr, ffh16, nullptr, nullptr,
                  B_*T_, FF_, C_, C_, C_, FF_, 0);
        h_gemm<0>(ffh16, wtFF2[l], ff2_b + (size_t)l*C_, tmp, nullptr, nullptr, nullptr,
                  B_*T_, C_, FF_, FF_, FF_, C_, 0);
        add_ln_kernel<<<B_*T_, 256>>>(tgt, tgt16, tmp, ln_w + (size_t)(l*3+2)*C_, ln_b + (size_t)(l*3+2)*C_);
    }

    {
        dim3 g(C_/32, T_/32, B_); dim3 bl(32, 8);
        transpose_out_kernel<<<g, bl>>>(tgt, out);
    }
}